// round 13
// baseline (speedup 1.0000x reference)
#include <cuda_runtime.h>
#include <cuda_fp16.h>
#include <math.h>
#include <stdint.h>

// ----------------------------------------------------------------------------
// LlamaAttention + H2O mask. fp16 tensor-core GEMMs (m16n8k16):
//   - mask-critical path (Wq, Wk, QK^T): fp16x2 3-product staged split.
//   - Output-0-only path (Wv, attn*V, Wo): plain fp16.
//   - Wq+Wk+Wv projections packed into ONE launch (grid z) so the small
//     K/V grids backfill Wq's tail wave. RoPE(Q)+RoPE(K) merged likewise.
// B=1, S=2048, HID=4096, NH=32, NKV=8, HD=128, GROUPS=4, HB=RB=204
// ----------------------------------------------------------------------------

#define S_LEN   2048
#define HID     4096
#define NH      32
#define NKV     8
#define HD      128
#define HB      204
#define RB      204
#define SEL     (S_LEN - RB)   // 1844

__device__ float g_Q [S_LEN * HID];
__device__ float g_K [S_LEN * NKV * HD];
__device__ float g_V [S_LEN * NKV * HD];
__device__ float g_S [(size_t)NH * S_LEN * S_LEN];
__device__ float g_O [S_LEN * HID];
__device__ float g_CS[NH * S_LEN];

// pack two fp32 (consecutive k) into one fp16x2 register (low = even k)
__device__ __forceinline__ uint32_t f2h2(float lo, float hi) {
    __half2 h = __floats2half2_rn(lo, hi);
    return *reinterpret_cast<uint32_t*>(&h);
}

// split-pack: big pair + small (residual) pair
__device__ __forceinline__ void split_pack(float x0, float x1,
                                           uint32_t& bp, uint32_t& sp) {
    __half b0 = __float2half_rn(x0);
    __half b1 = __float2half_rn(x1);
    float r0 = x0 - __half2float(b0);
    float r1 = x1 - __half2float(b1);
    __half2 bb = __halves2half2(b0, b1);
    __half2 ss = __halves2half2(__float2half_rn(r0), __float2half_rn(r1));
    bp = *reinterpret_cast<uint32_t*>(&bb);
    sp = *reinterpret_cast<uint32_t*>(&ss);
}

// D += A*B  (fp16 m16n8k16, fp32 accumulate)
__device__ __forceinline__ void mma_f16(float* c, const uint32_t* a, const uint32_t* b) {
    asm volatile(
        "mma.sync.aligned.m16n8k16.row.col.f32.f16.f16.f32 "
        "{%0,%1,%2,%3}, {%4,%5,%6,%7}, {%8,%9}, {%0,%1,%2,%3};"
        : "+f"(c[0]), "+f"(c[1]), "+f"(c[2]), "+f"(c[3])
        : "r"(a[0]), "r"(a[1]), "r"(a[2]), "r"(a[3]), "r"(b[0]), "r"(b[1]));
}

// D = A*B + 0 (fresh accumulation chain)
__device__ __forceinline__ void mma_f16_zero(float* d, const uint32_t* a, const uint32_t* b) {
    asm volatile(
        "mma.sync.aligned.m16n8k16.row.col.f32.f16.f16.f32 "
        "{%0,%1,%2,%3}, {%4,%5,%6,%7}, {%8,%9}, {%10,%11,%12,%13};"
        : "=f"(d[0]), "=f"(d[1]), "=f"(d[2]), "=f"(d[3])
        : "r"(a[0]), "r"(a[1]), "r"(a[2]), "r"(a[3]), "r"(b[0]), "r"(b[1]),
          "f"(0.0f), "f"(0.0f), "f"(0.0f), "f"(0.0f));
}

// 3-product staged: acc += aS*bB + aB*bS + aB*bB
__device__ __forceinline__ void mma3_staged(float* acc,
                                            const uint32_t* aB, const uint32_t* aS,
                                            const uint32_t* bB, const uint32_t* bS) {
    float tmp[4];
    mma_f16_zero(tmp, aS, bB);
    mma_f16(tmp, aB, bS);
    mma_f16(tmp, aB, bB);
    acc[0] += tmp[0];
    acc[1] += tmp[1];
    acc[2] += tmp[2];
    acc[3] += tmp[3];
}

// ============================================================================
// Shared staged-GEMM body: C = alpha * A * B^T, fp16x2 3-product split.
// ============================================================================
__device__ __forceinline__
void gemm_abt3_body(const float* __restrict__ A, const float* __restrict__ B,
                    float* __restrict__ C,
                    int K, int lda, int ldb, int ldc,
                    int bx, int by, float alpha)
{
    __shared__ uint32_t AsB[8][132];
    __shared__ uint32_t AsS[8][132];
    __shared__ uint32_t BsB[8][132];
    __shared__ uint32_t BsS[8][132];

    const int tid  = threadIdx.x;
    const int lane = tid & 31;
    const int wid  = tid >> 5;
    const int g    = lane >> 2;
    const int tig  = lane & 3;
    const int mbase = (wid >> 2) * 64;
    const int nbase = (wid & 3) * 32;

    const int lrow = tid >> 2;
    const int lcol = (tid & 3) * 4;
    const int kp0  = lcol >> 1;

    const float* Ab = A + (long)(by * 128) * lda;
    const float* Bb = B + (long)(bx * 128) * ldb;

    float acc[4][4][4];
#pragma unroll
    for (int i = 0; i < 4; i++)
#pragma unroll
        for (int j = 0; j < 4; j++)
#pragma unroll
            for (int k = 0; k < 4; k++) acc[i][j][k] = 0.0f;

    float4 ra[2], rb[2];
#pragma unroll
    for (int r = 0; r < 2; r++) {
        ra[r] = *(const float4*)(Ab + (long)(lrow + r * 64) * lda + lcol);
        rb[r] = *(const float4*)(Bb + (long)(lrow + r * 64) * ldb + lcol);
    }

    for (int kk = 0; kk < K; kk += 16) {
#pragma unroll
        for (int r = 0; r < 2; r++) {
            const int row = lrow + r * 64;
            split_pack(ra[r].x, ra[r].y, AsB[kp0    ][row], AsS[kp0    ][row]);
            split_pack(ra[r].z, ra[r].w, AsB[kp0 + 1][row], AsS[kp0 + 1][row]);
            split_pack(rb[r].x, rb[r].y, BsB[kp0    ][row], BsS[kp0    ][row]);
            split_pack(rb[r].z, rb[r].w, BsB[kp0 + 1][row], BsS[kp0 + 1][row]);
        }
        __syncthreads();

        if (kk + 16 < K) {
#pragma unroll
            for (int r = 0; r < 2; r++) {
                ra[r] = *(const float4*)(Ab + (long)(lrow + r * 64) * lda + kk + 16 + lcol);
                rb[r] = *(const float4*)(Bb + (long)(lrow + r * 64) * ldb + kk + 16 + lcol);
            }
        }

        {
            uint32_t afB[4][4], afS[4][4], bfB[4][2], bfS[4][2];
#pragma unroll
            for (int mt = 0; mt < 4; mt++) {
                const int r0 = mbase + mt * 16 + g;
                afB[mt][0] = AsB[tig    ][r0    ];
                afB[mt][1] = AsB[tig    ][r0 + 8];
                afB[mt][2] = AsB[tig + 4][r0    ];
                afB[mt][3] = AsB[tig + 4][r0 + 8];
                afS[mt][0] = AsS[tig    ][r0    ];
                afS[mt][1] = AsS[tig    ][r0 + 8];
                afS[mt][2] = AsS[tig + 4][r0    ];
                afS[mt][3] = AsS[tig + 4][r0 + 8];
            }
#pragma unroll
            for (int nt = 0; nt < 4; nt++) {
                const int c0 = nbase + nt * 8 + g;
                bfB[nt][0] = BsB[tig    ][c0];
                bfB[nt][1] = BsB[tig + 4][c0];
                bfS[nt][0] = BsS[tig    ][c0];
                bfS[nt][1] = BsS[tig + 4][c0];
            }
#pragma unroll
            for (int mt = 0; mt < 4; mt++)
#pragma unroll
                for (int nt = 0; nt < 4; nt++)
                    mma3_staged(acc[mt][nt], afB[mt], afS[mt], bfB[nt], bfS[nt]);
        }
        __syncthreads();
    }

#pragma unroll
    for (int mt = 0; mt < 4; mt++) {
#pragma unroll
        for (int nt = 0; nt < 4; nt++) {
            const int row0 = by * 128 + mbase + mt * 16 + g;
            const int col0 = bx * 128 + nbase + nt * 8 + 2 * tig;
            C[(long)row0 * ldc + col0    ] = alpha * acc[mt][nt][0];
            C[(long)row0 * ldc + col0 + 1] = alpha * acc[mt][nt][1];
            C[(long)(row0 + 8) * ldc + col0    ] = alpha * acc[mt][nt][2];
            C[(long)(row0 + 8) * ldc + col0 + 1] = alpha * acc[mt][nt][3];
        }
    }
}

// ============================================================================
// Shared plain-fp16 GEMM body: C = alpha * A * B^T.
// ============================================================================
__device__ __forceinline__
void gemm_abt_f16_body(const float* __restrict__ A, const float* __restrict__ B,
                       float* __restrict__ C,
                       int K, int lda, int ldb, int ldc,
                       int bx, int by, float alpha)
{
    __shared__ uint32_t As[8][132];
    __shared__ uint32_t Bs[8][132];

    const int tid  = threadIdx.x;
    const int lane = tid & 31;
    const int wid  = tid >> 5;
    const int g    = lane >> 2;
    const int tig  = lane & 3;
    const int mbase = (wid >> 2) * 64;
    const int nbase = (wid & 3) * 32;

    const int lrow = tid >> 2;
    const int lcol = (tid & 3) * 4;
    const int kp0  = lcol >> 1;

    const float* Ab = A + (long)(by * 128) * lda;
    const float* Bb = B + (long)(bx * 128) * ldb;

    float acc[4][4][4];
#pragma unroll
    for (int i = 0; i < 4; i++)
#pragma unroll
        for (int j = 0; j < 4; j++)
#pragma unroll
            for (int k = 0; k < 4; k++) acc[i][j][k] = 0.0f;

    float4 ra[2], rb[2];
#pragma unroll
    for (int r = 0; r < 2; r++) {
        ra[r] = *(const float4*)(Ab + (long)(lrow + r * 64) * lda + lcol);
        rb[r] = *(const float4*)(Bb + (long)(lrow + r * 64) * ldb + lcol);
    }

    for (int kk = 0; kk < K; kk += 16) {
#pragma unroll
        for (int r = 0; r < 2; r++) {
            const int row = lrow + r * 64;
            As[kp0    ][row] = f2h2(ra[r].x, ra[r].y);
            As[kp0 + 1][row] = f2h2(ra[r].z, ra[r].w);
            Bs[kp0    ][row] = f2h2(rb[r].x, rb[r].y);
            Bs[kp0 + 1][row] = f2h2(rb[r].z, rb[r].w);
        }
        __syncthreads();

        if (kk + 16 < K) {
#pragma unroll
            for (int r = 0; r < 2; r++) {
                ra[r] = *(const float4*)(Ab + (long)(lrow + r * 64) * lda + kk + 16 + lcol);
                rb[r] = *(const float4*)(Bb + (long)(lrow + r * 64) * ldb + kk + 16 + lcol);
            }
        }

        {
            uint32_t af[4][4], bf[4][2];
#pragma unroll
            for (int mt = 0; mt < 4; mt++) {
                const int r0 = mbase + mt * 16 + g;
                af[mt][0] = As[tig    ][r0    ];
                af[mt][1] = As[tig    ][r0 + 8];
                af[mt][2] = As[tig + 4][r0    ];
                af[mt][3] = As[tig + 4][r0 + 8];
            }
#pragma unroll
            for (int nt = 0; nt < 4; nt++) {
                const int c0 = nbase + nt * 8 + g;
                bf[nt][0] = Bs[tig    ][c0];
                bf[nt][1] = Bs[tig + 4][c0];
            }
#pragma unroll
            for (int mt = 0; mt < 4; mt++)
#pragma unroll
                for (int nt = 0; nt < 4; nt++)
                    mma_f16(acc[mt][nt], af[mt], bf[nt]);
        }
        __syncthreads();
    }

#pragma unroll
    for (int mt = 0; mt < 4; mt++) {
#pragma unroll
        for (int nt = 0; nt < 4; nt++) {
            const int row0 = by * 128 + mbase + mt * 16 + g;
            const int col0 = bx * 128 + nbase + nt * 8 + 2 * tig;
            C[(long)row0 * ldc + col0    ] = alpha * acc[mt][nt][0];
            C[(long)row0 * ldc + col0 + 1] = alpha * acc[mt][nt][1];
            C[(long)(row0 + 8) * ldc + col0    ] = alpha * acc[mt][nt][2];
            C[(long)(row0 + 8) * ldc + col0 + 1] = alpha * acc[mt][nt][3];
        }
    }
}

// ============================================================================
// Merged Q+K+V projection launch: grid (32, 16, 3).
// z=0: Q = H*Wq^T (staged). z=1: K = H*Wk^T (staged, bx<8).
// z=2: V = H*Wv^T (plain fp16, bx<8). Small grids backfill Wq's tail wave.
// ============================================================================
__global__ __launch_bounds__(256)
void gemm_qkv_proj(const float* __restrict__ H_,
                   const float* __restrict__ Wq, const float* __restrict__ Wk,
                   const float* __restrict__ Wv,
                   float* __restrict__ Q, float* __restrict__ K_,
                   float* __restrict__ V)
{
    const int z = blockIdx.z;
    if (z >= 1 && blockIdx.x >= (NKV * HD) / 128) return;
    if (z == 0) {
        gemm_abt3_body(H_, Wq, Q, HID, HID, HID, HID,
                       blockIdx.x, blockIdx.y, 1.0f);
    } else if (z == 1) {
        gemm_abt3_body(H_, Wk, K_, HID, HID, HID, NKV * HD,
                       blockIdx.x, blockIdx.y, 1.0f);
    } else {
        gemm_abt_f16_body(H_, Wv, V, HID, HID, HID, NKV * HD,
                          blockIdx.x, blockIdx.y, 1.0f);
    }
}

// ============================================================================
// Scores: staged 3-product, causal. grid (16, 16, 32).
// ============================================================================
__global__ __launch_bounds__(256)
void gemm_scores3h(const float* __restrict__ Q, const float* __restrict__ K_,
                   float* __restrict__ Sm, float alpha)
{
    const int h = blockIdx.z;
    const int bx = blockIdx.x, by = blockIdx.y;
    if (bx > by) return;
    gemm_abt3_body(Q + (long)h * HD, K_ + (long)(h >> 2) * HD,
                   Sm + (long)h * S_LEN * S_LEN,
                   HD, HID, NKV * HD, S_LEN, bx, by, alpha);
}

// ============================================================================
// Wo projection: plain fp16. grid (32, 16).
// ============================================================================
__global__ __launch_bounds__(256)
void gemm_wo_f16(const float* __restrict__ O, const float* __restrict__ Wo,
                 float* __restrict__ out)
{
    gemm_abt_f16_body(O, Wo, out, HID, HID, HID, HID,
                      blockIdx.x, blockIdx.y, 1.0f);
}

// ============================================================================
// Plain fp16 GEMM: C = alpha * A * B  (attn * V, per-head; B row-major K x N)
// causal: K limited to (by+1)*128.
// ============================================================================
__global__ __launch_bounds__(256)
void gemm_ab_f16(const float* __restrict__ A, const float* __restrict__ B,
                 float* __restrict__ C,
                 int K, int lda, int ldb, int ldc,
                 long aHS, long bHS, long cHS, int bShift,
                 float alpha, int causal)
{
    const int h = blockIdx.z;
    A += (long)h * aHS;
    B += (long)(h >> bShift) * bHS;
    C += (long)h * cHS;
    const int bx = blockIdx.x, by = blockIdx.y;

    __shared__ uint32_t As[8][132];
    __shared__ uint32_t Bs[8][132];

    const int tid  = threadIdx.x;
    const int lane = tid & 31;
    const int wid  = tid >> 5;
    const int g    = lane >> 2;
    const int tig  = lane & 3;
    const int mbase = (wid >> 2) * 64;
    const int nbase = (wid & 3) * 32;

    const int lrow  = tid >> 2;
    const int lcol  = (tid & 3) * 4;
    const int kp0   = lcol >> 1;
    const int brow  = tid >> 5;
    const int bcol4 = (tid & 31) * 4;

    const float* Ab = A + (long)(by * 128) * lda;

    const int Keff = causal ? (((by + 1) * 128 < K) ? (by + 1) * 128 : K) : K;

    float acc[4][4][4];
#pragma unroll
    for (int i = 0; i < 4; i++)
#pragma unroll
        for (int j = 0; j < 4; j++)
#pragma unroll
            for (int k = 0; k < 4; k++) acc[i][j][k] = 0.0f;

    float4 ra[2], rbl, rbh;
#pragma unroll
    for (int r = 0; r < 2; r++)
        ra[r] = *(const float4*)(Ab + (long)(lrow + r * 64) * lda + lcol);
    rbl = *(const float4*)(B + (long)(2 * brow    ) * ldb + bx * 128 + bcol4);
    rbh = *(const float4*)(B + (long)(2 * brow + 1) * ldb + bx * 128 + bcol4);

    for (int kk = 0; kk < Keff; kk += 16) {
#pragma unroll
        for (int r = 0; r < 2; r++) {
            const int row = lrow + r * 64;
            As[kp0    ][row] = f2h2(ra[r].x, ra[r].y);
            As[kp0 + 1][row] = f2h2(ra[r].z, ra[r].w);
        }
        Bs[brow][bcol4 + 0] = f2h2(rbl.x, rbh.x);
        Bs[brow][bcol4 + 1] = f2h2(rbl.y, rbh.y);
        Bs[brow][bcol4 + 2] = f2h2(rbl.z, rbh.z);
        Bs[brow][bcol4 + 3] = f2h2(rbl.w, rbh.w);
        __syncthreads();

        if (kk + 16 < Keff) {
#pragma unroll
            for (int r = 0; r < 2; r++)
                ra[r] = *(const float4*)(Ab + (long)(lrow + r * 64) * lda + kk + 16 + lcol);
            rbl = *(const float4*)(B + (long)(kk + 16 + 2 * brow    ) * ldb + bx * 128 + bcol4);
            rbh = *(const float4*)(B + (long)(kk + 16 + 2 * brow + 1) * ldb + bx * 128 + bcol4);
        }

        {
            uint32_t af[4][4], bf[4][2];
#pragma unroll
            for (int mt = 0; mt < 4; mt++) {
                const int r0 = mbase + mt * 16 + g;
                af[mt][0] = As[tig    ][r0    ];
                af[mt][1] = As[tig    ][r0 + 8];
                af[mt][2] = As[tig + 4][r0    ];
                af[mt][3] = As[tig + 4][r0 + 8];
            }
#pragma unroll
            for (int nt = 0; nt < 4; nt++) {
                const int c0 = nbase + nt * 8 + g;
                bf[nt][0] = Bs[tig    ][c0];
                bf[nt][1] = Bs[tig + 4][c0];
            }
#pragma unroll
            for (int mt = 0; mt < 4; mt++)
#pragma unroll
                for (int nt = 0; nt < 4; nt++)
                    mma_f16(acc[mt][nt], af[mt], bf[nt]);
        }
        __syncthreads();
    }

#pragma unroll
    for (int mt = 0; mt < 4; mt++) {
#pragma unroll
        for (int nt = 0; nt < 4; nt++) {
            const int row0 = by * 128 + mbase + mt * 16 + g;
            const int col0 = bx * 128 + nbase + nt * 8 + 2 * tig;
            C[(long)row0 * ldc + col0    ] = alpha * acc[mt][nt][0];
            C[(long)row0 * ldc + col0 + 1] = alpha * acc[mt][nt][1];
            C[(long)(row0 + 8) * ldc + col0    ] = alpha * acc[mt][nt][2];
            C[(long)(row0 + 8) * ldc + col0 + 1] = alpha * acc[mt][nt][3];
        }
    }
}

// ============================================================================
// Merged RoPE: first totQ threads handle Q (nh=NH), rest handle K (nh=NKV).
// ============================================================================
__global__ void rope_both_kernel(float* __restrict__ Q, float* __restrict__ K_,
                                 int totQ, int totAll)
{
    int idx = blockIdx.x * blockDim.x + threadIdx.x;
    if (idx >= totAll) return;
    float* X;
    int nh;
    if (idx < totQ) { X = Q;  nh = NH;  }
    else            { X = K_; nh = NKV; idx -= totQ; }
    int d = idx & 63;
    int h = (idx >> 6) % nh;
    int s = idx / (64 * nh);
    float e    = (float)(2 * d) * (1.0f / 128.0f);
    float invf = 1.0f / powf(10000.0f, e);
    float ang  = (float)s * invf;
    float c = cosf(ang), sn = sinf(ang);
    float* p = X + (long)s * (nh * HD) + h * HD;
    float x1 = p[d], x2 = p[d + 64];
    p[d]      = x1 * c - x2 * sn;
    p[d + 64] = x2 * c + x1 * sn;
}

// ============================================================================
// Causal row softmax, online max/sum; zero-fills diagonal block only.
// ============================================================================
__global__ __launch_bounds__(256)
void softmax_causal(float* __restrict__ Sm)
{
    const int q = blockIdx.x, h = blockIdx.y;
    float* row = Sm + ((long)h * S_LEN + q) * S_LEN;
    const int len = q + 1;
    const int tid = threadIdx.x;
    __shared__ float mred[256], sred[256];

    float m = -INFINITY, s = 0.0f;
    for (int i = tid; i < len; i += 256) {
        float x = row[i];
        float nm = fmaxf(m, x);
        s = s * expf(m - nm) + expf(x - nm);
        m = nm;
    }
    mred[tid] = m; sred[tid] = s; __syncthreads();
    for (int st = 128; st > 0; st >>= 1) {
        if (tid < st) {
            float m1 = mred[tid], s1 = sred[tid];
            float m2 = mred[tid + st], s2 = sred[tid + st];
            float nm = fmaxf(m1, m2);
            float sm = 0.0f;
            if (m1 > -INFINITY) sm += s1 * expf(m1 - nm);
            if (m2 > -INFINITY) sm += s2 * expf(m2 - nm);
            mred[tid] = nm; sred[tid] = sm;
        }
        __syncthreads();
    }
    const float M = mred[0];
    const float inv = 1.0f / sred[0];

    for (int i = tid; i < len; i += 256) row[i] = expf(row[i] - M) * inv;

    const int fillEnd = ((q >> 7) + 1) << 7;
    for (int i = len + tid; i < fillEnd; i += 256) row[i] = 0.0f;
}

// ============================================================================
// Column sums: cs[h][k] = sum_q attn[h][q][k] (lower triangle only).
// ============================================================================
__global__ __launch_bounds__(256)
void colsum_kernel(const float* __restrict__ attn, float* __restrict__ cs)
{
    const int k = blockIdx.x * 256 + threadIdx.x;
    const int h = blockIdx.y;
    const float* base = attn + (size_t)h * S_LEN * S_LEN;
    float s = 0.0f;
    for (int q = k; q < S_LEN; q++) s += base[(long)q * S_LEN + k];
    cs[h * S_LEN + k] = s;
}

// ============================================================================
// H2O mask: per head top-HB of colsum[0:SEL] + last RB columns.
// ============================================================================
__global__ __launch_bounds__(256)
void h2o_mask(const float* __restrict__ cs, float* __restrict__ mask)
{
    const int h = blockIdx.x;
    const int tid = threadIdx.x;
    __shared__ float vals[SEL];
    __shared__ float bval[256];
    __shared__ int   bidx[256];

    for (int i = tid; i < SEL; i += 256) vals[i] = cs[h * S_LEN + i];
    float* mrow = mask + h * (S_LEN + 1);
    for (int i = tid; i < S_LEN + 1; i += 256)
        mrow[i] = (i >= (S_LEN + 1 - RB)) ? 1.0f : 0.0f;
    __syncthreads();

    for (int it = 0; it < HB; it++) {
        float best = -INFINITY; int bi = SEL;
        for (int i = tid; i < SEL; i += 256) {
            float v = vals[i];
            if (v > best) { best = v; bi = i; }
        }
        bval[tid] = best; bidx[tid] = bi; __syncthreads();
        for (int s = 128; s > 0; s >>= 1) {
            if (tid < s) {
                if (bval[tid + s] > bval[tid] ||
                    (bval[tid + s] == bval[tid] && bidx[tid + s] < bidx[tid])) {
                    bval[tid] = bval[tid + s];
                    bidx[tid] = bidx[tid + s];
                }
            }
            __syncthreads();
        }
        if (tid == 0) {
            mrow[bidx[0]] = 1.0f;
            vals[bidx[0]] = -INFINITY;
        }
        __syncthreads();
    }
}

// ============================================================================
// Host launcher
// ============================================================================
extern "C" void kernel_launch(void* const* d_in, const int* in_sizes, int n_in,
                              void* d_out, int out_size)
{
    const float* H  = (const float*)d_in[0];
    const float* Wq = (const float*)d_in[1];
    const float* Wk = (const float*)d_in[2];
    const float* Wv = (const float*)d_in[3];
    const float* Wo = (const float*)d_in[4];
    float* out = (float*)d_out;

    float *Q, *K, *V, *Sm, *O, *CS;
    cudaGetSymbolAddress((void**)&Q,  g_Q);
    cudaGetSymbolAddress((void**)&K,  g_K);
    cudaGetSymbolAddress((void**)&V,  g_V);
    cudaGetSymbolAddress((void**)&Sm, g_S);
    cudaGetSymbolAddress((void**)&O,  g_O);
    cudaGetSymbolAddress((void**)&CS, g_CS);

    const float inv_sqrt_hd = 0.08838834764831845f; // 1/sqrt(128)

    // Q + K + V projections packed into one launch
    gemm_qkv_proj<<<dim3(HID / 128, S_LEN / 128, 3), 256>>>(
        H, Wq, Wk, Wv, Q, K, V);

    // RoPE (Q and K merged)
    {
        int totQ   = S_LEN * NH * 64;
        int totAll = totQ + S_LEN * NKV * 64;
        rope_both_kernel<<<(totAll + 255) / 256, 256>>>(Q, K, totQ, totAll);
    }

    // scores = Q K^T / sqrt(HD): staged 3-product, causal
    gemm_scores3h<<<dim3(S_LEN / 128, S_LEN / 128, NH), 256>>>(
        Q, K, Sm, inv_sqrt_hd);

    // softmax (online; zero-fills diagonal blocks only)
    softmax_causal<<<dim3(S_LEN, NH), 256>>>(Sm);

    // column sums
    colsum_kernel<<<dim3(S_LEN / 256, NH), 256>>>(Sm, CS);

    // context = attn * V : plain fp16
    gemm_ab_f16<<<dim3(HD / 128, S_LEN / 128, NH), 256>>>(
        Sm, V, O, S_LEN, S_LEN, NKV * HD, HID,
        (long)S_LEN * S_LEN, HD, HD, 2, 1.0f, 1);

    // attn_output = O * Wo^T : plain fp16
    gemm_wo_f16<<<dim3(HID / 128, S_LEN / 128), 256>>>(O, Wo, out);

    // H2O mask
    {
        size_t maskOff = (size_t)out_size - (size_t)NH * (S_LEN + 1);
        h2o_mask<<<NH, 256>>>(CS, out + maskOff);
    }
}

// round 14
// speedup vs baseline: 1.0350x; 1.0350x over previous
#include <cuda_runtime.h>
#include <cuda_fp16.h>
#include <math.h>
#include <stdint.h>

// ----------------------------------------------------------------------------
// LlamaAttention + H2O mask. fp16 tensor-core GEMMs (m16n8k16):
//   - mask-critical path (Wq, Wk, QK^T): fp16x2 3-product staged split.
//     Wq+Wk packed into ONE launch (same body => same resource footprint).
//   - Output-0-only path (Wv, attn*V, Wo): plain fp16, separate launches
//     (mixing bodies in one kernel regressed occupancy in R13).
//   - RoPE(Q)+RoPE(K) merged; softmax uses __expf (MUFU) -- error ~1e-6,
//     3 orders below the perturbation scale the mask already tolerates.
// B=1, S=2048, HID=4096, NH=32, NKV=8, HD=128, GROUPS=4, HB=RB=204
// ----------------------------------------------------------------------------

#define S_LEN   2048
#define HID     4096
#define NH      32
#define NKV     8
#define HD      128
#define HB      204
#define RB      204
#define SEL     (S_LEN - RB)   // 1844

__device__ float g_Q [S_LEN * HID];
__device__ float g_K [S_LEN * NKV * HD];
__device__ float g_V [S_LEN * NKV * HD];
__device__ float g_S [(size_t)NH * S_LEN * S_LEN];
__device__ float g_O [S_LEN * HID];
__device__ float g_CS[NH * S_LEN];

// pack two fp32 (consecutive k) into one fp16x2 register (low = even k)
__device__ __forceinline__ uint32_t f2h2(float lo, float hi) {
    __half2 h = __floats2half2_rn(lo, hi);
    return *reinterpret_cast<uint32_t*>(&h);
}

// split-pack: big pair + small (residual) pair
__device__ __forceinline__ void split_pack(float x0, float x1,
                                           uint32_t& bp, uint32_t& sp) {
    __half b0 = __float2half_rn(x0);
    __half b1 = __float2half_rn(x1);
    float r0 = x0 - __half2float(b0);
    float r1 = x1 - __half2float(b1);
    __half2 bb = __halves2half2(b0, b1);
    __half2 ss = __halves2half2(__float2half_rn(r0), __float2half_rn(r1));
    bp = *reinterpret_cast<uint32_t*>(&bb);
    sp = *reinterpret_cast<uint32_t*>(&ss);
}

// D += A*B  (fp16 m16n8k16, fp32 accumulate)
__device__ __forceinline__ void mma_f16(float* c, const uint32_t* a, const uint32_t* b) {
    asm volatile(
        "mma.sync.aligned.m16n8k16.row.col.f32.f16.f16.f32 "
        "{%0,%1,%2,%3}, {%4,%5,%6,%7}, {%8,%9}, {%0,%1,%2,%3};"
        : "+f"(c[0]), "+f"(c[1]), "+f"(c[2]), "+f"(c[3])
        : "r"(a[0]), "r"(a[1]), "r"(a[2]), "r"(a[3]), "r"(b[0]), "r"(b[1]));
}

// D = A*B + 0 (fresh accumulation chain)
__device__ __forceinline__ void mma_f16_zero(float* d, const uint32_t* a, const uint32_t* b) {
    asm volatile(
        "mma.sync.aligned.m16n8k16.row.col.f32.f16.f16.f32 "
        "{%0,%1,%2,%3}, {%4,%5,%6,%7}, {%8,%9}, {%10,%11,%12,%13};"
        : "=f"(d[0]), "=f"(d[1]), "=f"(d[2]), "=f"(d[3])
        : "r"(a[0]), "r"(a[1]), "r"(a[2]), "r"(a[3]), "r"(b[0]), "r"(b[1]),
          "f"(0.0f), "f"(0.0f), "f"(0.0f), "f"(0.0f));
}

// 3-product staged: acc += aS*bB + aB*bS + aB*bB
__device__ __forceinline__ void mma3_staged(float* acc,
                                            const uint32_t* aB, const uint32_t* aS,
                                            const uint32_t* bB, const uint32_t* bS) {
    float tmp[4];
    mma_f16_zero(tmp, aS, bB);
    mma_f16(tmp, aB, bS);
    mma_f16(tmp, aB, bB);
    acc[0] += tmp[0];
    acc[1] += tmp[1];
    acc[2] += tmp[2];
    acc[3] += tmp[3];
}

// ============================================================================
// Shared staged-GEMM body: C = alpha * A * B^T, fp16x2 3-product split.
// ============================================================================
__device__ __forceinline__
void gemm_abt3_body(const float* __restrict__ A, const float* __restrict__ B,
                    float* __restrict__ C,
                    int K, int lda, int ldb, int ldc,
                    int bx, int by, float alpha)
{
    __shared__ uint32_t AsB[8][132];
    __shared__ uint32_t AsS[8][132];
    __shared__ uint32_t BsB[8][132];
    __shared__ uint32_t BsS[8][132];

    const int tid  = threadIdx.x;
    const int lane = tid & 31;
    const int wid  = tid >> 5;
    const int g    = lane >> 2;
    const int tig  = lane & 3;
    const int mbase = (wid >> 2) * 64;
    const int nbase = (wid & 3) * 32;

    const int lrow = tid >> 2;
    const int lcol = (tid & 3) * 4;
    const int kp0  = lcol >> 1;

    const float* Ab = A + (long)(by * 128) * lda;
    const float* Bb = B + (long)(bx * 128) * ldb;

    float acc[4][4][4];
#pragma unroll
    for (int i = 0; i < 4; i++)
#pragma unroll
        for (int j = 0; j < 4; j++)
#pragma unroll
            for (int k = 0; k < 4; k++) acc[i][j][k] = 0.0f;

    float4 ra[2], rb[2];
#pragma unroll
    for (int r = 0; r < 2; r++) {
        ra[r] = *(const float4*)(Ab + (long)(lrow + r * 64) * lda + lcol);
        rb[r] = *(const float4*)(Bb + (long)(lrow + r * 64) * ldb + lcol);
    }

    for (int kk = 0; kk < K; kk += 16) {
#pragma unroll
        for (int r = 0; r < 2; r++) {
            const int row = lrow + r * 64;
            split_pack(ra[r].x, ra[r].y, AsB[kp0    ][row], AsS[kp0    ][row]);
            split_pack(ra[r].z, ra[r].w, AsB[kp0 + 1][row], AsS[kp0 + 1][row]);
            split_pack(rb[r].x, rb[r].y, BsB[kp0    ][row], BsS[kp0    ][row]);
            split_pack(rb[r].z, rb[r].w, BsB[kp0 + 1][row], BsS[kp0 + 1][row]);
        }
        __syncthreads();

        if (kk + 16 < K) {
#pragma unroll
            for (int r = 0; r < 2; r++) {
                ra[r] = *(const float4*)(Ab + (long)(lrow + r * 64) * lda + kk + 16 + lcol);
                rb[r] = *(const float4*)(Bb + (long)(lrow + r * 64) * ldb + kk + 16 + lcol);
            }
        }

        {
            uint32_t afB[4][4], afS[4][4], bfB[4][2], bfS[4][2];
#pragma unroll
            for (int mt = 0; mt < 4; mt++) {
                const int r0 = mbase + mt * 16 + g;
                afB[mt][0] = AsB[tig    ][r0    ];
                afB[mt][1] = AsB[tig    ][r0 + 8];
                afB[mt][2] = AsB[tig + 4][r0    ];
                afB[mt][3] = AsB[tig + 4][r0 + 8];
                afS[mt][0] = AsS[tig    ][r0    ];
                afS[mt][1] = AsS[tig    ][r0 + 8];
                afS[mt][2] = AsS[tig + 4][r0    ];
                afS[mt][3] = AsS[tig + 4][r0 + 8];
            }
#pragma unroll
            for (int nt = 0; nt < 4; nt++) {
                const int c0 = nbase + nt * 8 + g;
                bfB[nt][0] = BsB[tig    ][c0];
                bfB[nt][1] = BsB[tig + 4][c0];
                bfS[nt][0] = BsS[tig    ][c0];
                bfS[nt][1] = BsS[tig + 4][c0];
            }
#pragma unroll
            for (int mt = 0; mt < 4; mt++)
#pragma unroll
                for (int nt = 0; nt < 4; nt++)
                    mma3_staged(acc[mt][nt], afB[mt], afS[mt], bfB[nt], bfS[nt]);
        }
        __syncthreads();
    }

#pragma unroll
    for (int mt = 0; mt < 4; mt++) {
#pragma unroll
        for (int nt = 0; nt < 4; nt++) {
            const int row0 = by * 128 + mbase + mt * 16 + g;
            const int col0 = bx * 128 + nbase + nt * 8 + 2 * tig;
            C[(long)row0 * ldc + col0    ] = alpha * acc[mt][nt][0];
            C[(long)row0 * ldc + col0 + 1] = alpha * acc[mt][nt][1];
            C[(long)(row0 + 8) * ldc + col0    ] = alpha * acc[mt][nt][2];
            C[(long)(row0 + 8) * ldc + col0 + 1] = alpha * acc[mt][nt][3];
        }
    }
}

// ============================================================================
// Merged Q+K projection launch: grid (32, 16, 2). Same body both z => same
// resource footprint (packing rule from R13 post-mortem).
// ============================================================================
__global__ __launch_bounds__(256)
void gemm_qk_proj(const float* __restrict__ H_,
                  const float* __restrict__ Wq, const float* __restrict__ Wk,
                  float* __restrict__ Q, float* __restrict__ K_)
{
    const int z = blockIdx.z;
    if (z == 1 && blockIdx.x >= (NKV * HD) / 128) return;
    const float* B = z ? Wk : Wq;
    float*       C = z ? K_ : Q;
    const int  ldc = z ? (NKV * HD) : HID;
    gemm_abt3_body(H_, B, C, HID, HID, HID, ldc,
                   blockIdx.x, blockIdx.y, 1.0f);
}

// ============================================================================
// Scores: staged 3-product, causal. grid (16, 16, 32).
// ============================================================================
__global__ __launch_bounds__(256)
void gemm_scores3h(const float* __restrict__ Q, const float* __restrict__ K_,
                   float* __restrict__ Sm, float alpha)
{
    const int h = blockIdx.z;
    const int bx = blockIdx.x, by = blockIdx.y;
    if (bx > by) return;
    gemm_abt3_body(Q + (long)h * HD, K_ + (long)(h >> 2) * HD,
                   Sm + (long)h * S_LEN * S_LEN,
                   HD, HID, NKV * HD, S_LEN, bx, by, alpha);
}

// ============================================================================
// Plain fp16 GEMM: C = alpha * A * B^T  (Wv, Wo projections; Output 0 only)
// ============================================================================
__global__ __launch_bounds__(256)
void gemm_abt_f16(const float* __restrict__ A, const float* __restrict__ B,
                  float* __restrict__ C,
                  int K, int lda, int ldb, int ldc, float alpha)
{
    const int bx = blockIdx.x, by = blockIdx.y;

    __shared__ uint32_t As[8][132];
    __shared__ uint32_t Bs[8][132];

    const int tid  = threadIdx.x;
    const int lane = tid & 31;
    const int wid  = tid >> 5;
    const int g    = lane >> 2;
    const int tig  = lane & 3;
    const int mbase = (wid >> 2) * 64;
    const int nbase = (wid & 3) * 32;

    const int lrow = tid >> 2;
    const int lcol = (tid & 3) * 4;
    const int kp0  = lcol >> 1;

    const float* Ab = A + (long)(by * 128) * lda;
    const float* Bb = B + (long)(bx * 128) * ldb;

    float acc[4][4][4];
#pragma unroll
    for (int i = 0; i < 4; i++)
#pragma unroll
        for (int j = 0; j < 4; j++)
#pragma unroll
            for (int k = 0; k < 4; k++) acc[i][j][k] = 0.0f;

    float4 ra[2], rb[2];
#pragma unroll
    for (int r = 0; r < 2; r++) {
        ra[r] = *(const float4*)(Ab + (long)(lrow + r * 64) * lda + lcol);
        rb[r] = *(const float4*)(Bb + (long)(lrow + r * 64) * ldb + lcol);
    }

    for (int kk = 0; kk < K; kk += 16) {
#pragma unroll
        for (int r = 0; r < 2; r++) {
            const int row = lrow + r * 64;
            As[kp0    ][row] = f2h2(ra[r].x, ra[r].y);
            As[kp0 + 1][row] = f2h2(ra[r].z, ra[r].w);
            Bs[kp0    ][row] = f2h2(rb[r].x, rb[r].y);
            Bs[kp0 + 1][row] = f2h2(rb[r].z, rb[r].w);
        }
        __syncthreads();

        if (kk + 16 < K) {
#pragma unroll
            for (int r = 0; r < 2; r++) {
                ra[r] = *(const float4*)(Ab + (long)(lrow + r * 64) * lda + kk + 16 + lcol);
                rb[r] = *(const float4*)(Bb + (long)(lrow + r * 64) * ldb + kk + 16 + lcol);
            }
        }

        {
            uint32_t af[4][4], bf[4][2];
#pragma unroll
            for (int mt = 0; mt < 4; mt++) {
                const int r0 = mbase + mt * 16 + g;
                af[mt][0] = As[tig    ][r0    ];
                af[mt][1] = As[tig    ][r0 + 8];
                af[mt][2] = As[tig + 4][r0    ];
                af[mt][3] = As[tig + 4][r0 + 8];
            }
#pragma unroll
            for (int nt = 0; nt < 4; nt++) {
                const int c0 = nbase + nt * 8 + g;
                bf[nt][0] = Bs[tig    ][c0];
                bf[nt][1] = Bs[tig + 4][c0];
            }
#pragma unroll
            for (int mt = 0; mt < 4; mt++)
#pragma unroll
                for (int nt = 0; nt < 4; nt++)
                    mma_f16(acc[mt][nt], af[mt], bf[nt]);
        }
        __syncthreads();
    }

#pragma unroll
    for (int mt = 0; mt < 4; mt++) {
#pragma unroll
        for (int nt = 0; nt < 4; nt++) {
            const int row0 = by * 128 + mbase + mt * 16 + g;
            const int col0 = bx * 128 + nbase + nt * 8 + 2 * tig;
            C[(long)row0 * ldc + col0    ] = alpha * acc[mt][nt][0];
            C[(long)row0 * ldc + col0 + 1] = alpha * acc[mt][nt][1];
            C[(long)(row0 + 8) * ldc + col0    ] = alpha * acc[mt][nt][2];
            C[(long)(row0 + 8) * ldc + col0 + 1] = alpha * acc[mt][nt][3];
        }
    }
}

// ============================================================================
// Plain fp16 GEMM: C = alpha * A * B  (attn * V, per-head; B row-major K x N)
// causal: K limited to (by+1)*128.
// ============================================================================
__global__ __launch_bounds__(256)
void gemm_ab_f16(const float* __restrict__ A, const float* __restrict__ B,
                 float* __restrict__ C,
                 int K, int lda, int ldb, int ldc,
                 long aHS, long bHS, long cHS, int bShift,
                 float alpha, int causal)
{
    const int h = blockIdx.z;
    A += (long)h * aHS;
    B += (long)(h >> bShift) * bHS;
    C += (long)h * cHS;
    const int bx = blockIdx.x, by = blockIdx.y;

    __shared__ uint32_t As[8][132];
    __shared__ uint32_t Bs[8][132];

    const int tid  = threadIdx.x;
    const int lane = tid & 31;
    const int wid  = tid >> 5;
    const int g    = lane >> 2;
    const int tig  = lane & 3;
    const int mbase = (wid >> 2) * 64;
    const int nbase = (wid & 3) * 32;

    const int lrow  = tid >> 2;
    const int lcol  = (tid & 3) * 4;
    const int kp0   = lcol >> 1;
    const int brow  = tid >> 5;
    const int bcol4 = (tid & 31) * 4;

    const float* Ab = A + (long)(by * 128) * lda;

    const int Keff = causal ? (((by + 1) * 128 < K) ? (by + 1) * 128 : K) : K;

    float acc[4][4][4];
#pragma unroll
    for (int i = 0; i < 4; i++)
#pragma unroll
        for (int j = 0; j < 4; j++)
#pragma unroll
            for (int k = 0; k < 4; k++) acc[i][j][k] = 0.0f;

    float4 ra[2], rbl, rbh;
#pragma unroll
    for (int r = 0; r < 2; r++)
        ra[r] = *(const float4*)(Ab + (long)(lrow + r * 64) * lda + lcol);
    rbl = *(const float4*)(B + (long)(2 * brow    ) * ldb + bx * 128 + bcol4);
    rbh = *(const float4*)(B + (long)(2 * brow + 1) * ldb + bx * 128 + bcol4);

    for (int kk = 0; kk < Keff; kk += 16) {
#pragma unroll
        for (int r = 0; r < 2; r++) {
            const int row = lrow + r * 64;
            As[kp0    ][row] = f2h2(ra[r].x, ra[r].y);
            As[kp0 + 1][row] = f2h2(ra[r].z, ra[r].w);
        }
        Bs[brow][bcol4 + 0] = f2h2(rbl.x, rbh.x);
        Bs[brow][bcol4 + 1] = f2h2(rbl.y, rbh.y);
        Bs[brow][bcol4 + 2] = f2h2(rbl.z, rbh.z);
        Bs[brow][bcol4 + 3] = f2h2(rbl.w, rbh.w);
        __syncthreads();

        if (kk + 16 < Keff) {
#pragma unroll
            for (int r = 0; r < 2; r++)
                ra[r] = *(const float4*)(Ab + (long)(lrow + r * 64) * lda + kk + 16 + lcol);
            rbl = *(const float4*)(B + (long)(kk + 16 + 2 * brow    ) * ldb + bx * 128 + bcol4);
            rbh = *(const float4*)(B + (long)(kk + 16 + 2 * brow + 1) * ldb + bx * 128 + bcol4);
        }

        {
            uint32_t af[4][4], bf[4][2];
#pragma unroll
            for (int mt = 0; mt < 4; mt++) {
                const int r0 = mbase + mt * 16 + g;
                af[mt][0] = As[tig    ][r0    ];
                af[mt][1] = As[tig    ][r0 + 8];
                af[mt][2] = As[tig + 4][r0    ];
                af[mt][3] = As[tig + 4][r0 + 8];
            }
#pragma unroll
            for (int nt = 0; nt < 4; nt++) {
                const int c0 = nbase + nt * 8 + g;
                bf[nt][0] = Bs[tig    ][c0];
                bf[nt][1] = Bs[tig + 4][c0];
            }
#pragma unroll
            for (int mt = 0; mt < 4; mt++)
#pragma unroll
                for (int nt = 0; nt < 4; nt++)
                    mma_f16(acc[mt][nt], af[mt], bf[nt]);
        }
        __syncthreads();
    }

#pragma unroll
    for (int mt = 0; mt < 4; mt++) {
#pragma unroll
        for (int nt = 0; nt < 4; nt++) {
            const int row0 = by * 128 + mbase + mt * 16 + g;
            const int col0 = bx * 128 + nbase + nt * 8 + 2 * tig;
            C[(long)row0 * ldc + col0    ] = alpha * acc[mt][nt][0];
            C[(long)row0 * ldc + col0 + 1] = alpha * acc[mt][nt][1];
            C[(long)(row0 + 8) * ldc + col0    ] = alpha * acc[mt][nt][2];
            C[(long)(row0 + 8) * ldc + col0 + 1] = alpha * acc[mt][nt][3];
        }
    }
}

// ============================================================================
// Merged RoPE: first totQ threads handle Q (nh=NH), rest handle K (nh=NKV).
// ============================================================================
__global__ void rope_both_kernel(float* __restrict__ Q, float* __restrict__ K_,
                                 int totQ, int totAll)
{
    int idx = blockIdx.x * blockDim.x + threadIdx.x;
    if (idx >= totAll) return;
    float* X;
    int nh;
    if (idx < totQ) { X = Q;  nh = NH;  }
    else            { X = K_; nh = NKV; idx -= totQ; }
    int d = idx & 63;
    int h = (idx >> 6) % nh;
    int s = idx / (64 * nh);
    float e    = (float)(2 * d) * (1.0f / 128.0f);
    float invf = 1.0f / powf(10000.0f, e);
    float ang  = (float)s * invf;
    float c = cosf(ang), sn = sinf(ang);
    float* p = X + (long)s * (nh * HD) + h * HD;
    float x1 = p[d], x2 = p[d + 64];
    p[d]      = x1 * c - x2 * sn;
    p[d + 64] = x2 * c + x1 * sn;
}

// ============================================================================
// Causal row softmax, online max/sum with __expf (MUFU); zero-fills diagonal
// block only.
// ============================================================================
__global__ __launch_bounds__(256)
void softmax_causal(float* __restrict__ Sm)
{
    const int q = blockIdx.x, h = blockIdx.y;
    float* row = Sm + ((long)h * S_LEN + q) * S_LEN;
    const int len = q + 1;
    const int tid = threadIdx.x;
    __shared__ float mred[256], sred[256];

    float m = -INFINITY, s = 0.0f;
    for (int i = tid; i < len; i += 256) {
        float x = row[i];
        float nm = fmaxf(m, x);
        s = s * __expf(m - nm) + __expf(x - nm);
        m = nm;
    }
    mred[tid] = m; sred[tid] = s; __syncthreads();
    for (int st = 128; st > 0; st >>= 1) {
        if (tid < st) {
            float m1 = mred[tid], s1 = sred[tid];
            float m2 = mred[tid + st], s2 = sred[tid + st];
            float nm = fmaxf(m1, m2);
            float sm = 0.0f;
            if (m1 > -INFINITY) sm += s1 * __expf(m1 - nm);
            if (m2 > -INFINITY) sm += s2 * __expf(m2 - nm);
            mred[tid] = nm; sred[tid] = sm;
        }
        __syncthreads();
    }
    const float M = mred[0];
    const float inv = 1.0f / sred[0];

    for (int i = tid; i < len; i += 256) row[i] = __expf(row[i] - M) * inv;

    const int fillEnd = ((q >> 7) + 1) << 7;
    for (int i = len + tid; i < fillEnd; i += 256) row[i] = 0.0f;
}

// ============================================================================
// Column sums: cs[h][k] = sum_q attn[h][q][k] (lower triangle only).
// ============================================================================
__global__ __launch_bounds__(256)
void colsum_kernel(const float* __restrict__ attn, float* __restrict__ cs)
{
    const int k = blockIdx.x * 256 + threadIdx.x;
    const int h = blockIdx.y;
    const float* base = attn + (size_t)h * S_LEN * S_LEN;
    float s = 0.0f;
    for (int q = k; q < S_LEN; q++) s += base[(long)q * S_LEN + k];
    cs[h * S_LEN + k] = s;
}

// ============================================================================
// H2O mask: per head top-HB of colsum[0:SEL] + last RB columns.
// ============================================================================
__global__ __launch_bounds__(256)
void h2o_mask(const float* __restrict__ cs, float* __restrict__ mask)
{
    const int h = blockIdx.x;
    const int tid = threadIdx.x;
    __shared__ float vals[SEL];
    __shared__ float bval[256];
    __shared__ int   bidx[256];

    for (int i = tid; i < SEL; i += 256) vals[i] = cs[h * S_LEN + i];
    float* mrow = mask + h * (S_LEN + 1);
    for (int i = tid; i < S_LEN + 1; i += 256)
        mrow[i] = (i >= (S_LEN + 1 - RB)) ? 1.0f : 0.0f;
    __syncthreads();

    for (int it = 0; it < HB; it++) {
        float best = -INFINITY; int bi = SEL;
        for (int i = tid; i < SEL; i += 256) {
            float v = vals[i];
            if (v > best) { best = v; bi = i; }
        }
        bval[tid] = best; bidx[tid] = bi; __syncthreads();
        for (int s = 128; s > 0; s >>= 1) {
            if (tid < s) {
                if (bval[tid + s] > bval[tid] ||
                    (bval[tid + s] == bval[tid] && bidx[tid + s] < bidx[tid])) {
                    bval[tid] = bval[tid + s];
                    bidx[tid] = bidx[tid + s];
                }
            }
            __syncthreads();
        }
        if (tid == 0) {
            mrow[bidx[0]] = 1.0f;
            vals[bidx[0]] = -INFINITY;
        }
        __syncthreads();
    }
}

// ============================================================================
// Host launcher
// ============================================================================
extern "C" void kernel_launch(void* const* d_in, const int* in_sizes, int n_in,
                              void* d_out, int out_size)
{
    const float* H  = (const float*)d_in[0];
    const float* Wq = (const float*)d_in[1];
    const float* Wk = (const float*)d_in[2];
    const float* Wv = (const float*)d_in[3];
    const float* Wo = (const float*)d_in[4];
    float* out = (float*)d_out;

    float *Q, *K, *V, *Sm, *O, *CS;
    cudaGetSymbolAddress((void**)&Q,  g_Q);
    cudaGetSymbolAddress((void**)&K,  g_K);
    cudaGetSymbolAddress((void**)&V,  g_V);
    cudaGetSymbolAddress((void**)&Sm, g_S);
    cudaGetSymbolAddress((void**)&O,  g_O);
    cudaGetSymbolAddress((void**)&CS, g_CS);

    const float inv_sqrt_hd = 0.08838834764831845f; // 1/sqrt(128)

    // Q + K projections merged (same body => same footprint)
    gemm_qk_proj<<<dim3(HID / 128, S_LEN / 128, 2), 256>>>(H, Wq, Wk, Q, K);

    // V projection: plain fp16, separate launch
    gemm_abt_f16<<<dim3((NKV * HD) / 128, S_LEN / 128, 1), 256>>>(
        H, Wv, V, HID, HID, HID, NKV * HD, 1.0f);

    // RoPE (Q and K merged)
    {
        int totQ   = S_LEN * NH * 64;
        int totAll = totQ + S_LEN * NKV * 64;
        rope_both_kernel<<<(totAll + 255) / 256, 256>>>(Q, K, totQ, totAll);
    }

    // scores = Q K^T / sqrt(HD): staged 3-product, causal
    gemm_scores3h<<<dim3(S_LEN / 128, S_LEN / 128, NH), 256>>>(
        Q, K, Sm, inv_sqrt_hd);

    // softmax (online, __expf; zero-fills diagonal blocks only)
    softmax_causal<<<dim3(S_LEN, NH), 256>>>(Sm);

    // column sums
    colsum_kernel<<<dim3(S_LEN / 256, NH), 256>>>(Sm, CS);

    // context = attn * V : plain fp16
    gemm_ab_f16<<<dim3(HD / 128, S_LEN / 128, NH), 256>>>(
        Sm, V, O, S_LEN, S_LEN, NKV * HD, HID,
        (long)S_LEN * S_LEN, HD, HD, 2, 1.0f, 1);

    // attn_output = O * Wo^T : plain fp16
    gemm_abt_f16<<<dim3(HID / 128, S_LEN / 128, 1), 256>>>(
        O, Wo, out, HID, HID, HID, HID, 1.0f);

    // H2O mask
    {
        size_t maskOff = (size_t)out_size - (size_t)NH * (S_LEN + 1);
        h2o_mask<<<NH, 256>>>(CS, out + maskOff);
    }
}

// round 15
// speedup vs baseline: 1.1028x; 1.0655x over previous
#include <cuda_runtime.h>
#include <cuda_fp16.h>
#include <math.h>
#include <stdint.h>

// ----------------------------------------------------------------------------
// LlamaAttention + H2O mask. fp16 tensor-core GEMMs (m16n8k16):
//   - mask-critical path (Wq, Wk, QK^T): fp16x2 3-product staged split.
//     Wq+Wk packed into ONE launch (same body => same resource footprint).
//   - Output-0-only path (Wv, attn*V, Wo): plain fp16.
//   - smem fragment arrays padded to 136 words/row (stride == 8 mod 32):
//     makes ALL fragment LDS conflict-free (was 2-way at 132). R14 ncu:
//     L1 80.6% on scores -- smem bank conflicts were the binding resource.
// B=1, S=2048, HID=4096, NH=32, NKV=8, HD=128, GROUPS=4, HB=RB=204
// ----------------------------------------------------------------------------

#define S_LEN   2048
#define HID     4096
#define NH      32
#define NKV     8
#define HD      128
#define HB      204
#define RB      204
#define SEL     (S_LEN - RB)   // 1844
#define SPAD    136            // smem row stride (words): 8 mod 32 banks

__device__ float g_Q [S_LEN * HID];
__device__ float g_K [S_LEN * NKV * HD];
__device__ float g_V [S_LEN * NKV * HD];
__device__ float g_S [(size_t)NH * S_LEN * S_LEN];
__device__ float g_O [S_LEN * HID];
__device__ float g_CS[NH * S_LEN];

// pack two fp32 (consecutive k) into one fp16x2 register (low = even k)
__device__ __forceinline__ uint32_t f2h2(float lo, float hi) {
    __half2 h = __floats2half2_rn(lo, hi);
    return *reinterpret_cast<uint32_t*>(&h);
}

// split-pack: big pair + small (residual) pair
__device__ __forceinline__ void split_pack(float x0, float x1,
                                           uint32_t& bp, uint32_t& sp) {
    __half b0 = __float2half_rn(x0);
    __half b1 = __float2half_rn(x1);
    float r0 = x0 - __half2float(b0);
    float r1 = x1 - __half2float(b1);
    __half2 bb = __halves2half2(b0, b1);
    __half2 ss = __halves2half2(__float2half_rn(r0), __float2half_rn(r1));
    bp = *reinterpret_cast<uint32_t*>(&bb);
    sp = *reinterpret_cast<uint32_t*>(&ss);
}

// D += A*B  (fp16 m16n8k16, fp32 accumulate)
__device__ __forceinline__ void mma_f16(float* c, const uint32_t* a, const uint32_t* b) {
    asm volatile(
        "mma.sync.aligned.m16n8k16.row.col.f32.f16.f16.f32 "
        "{%0,%1,%2,%3}, {%4,%5,%6,%7}, {%8,%9}, {%0,%1,%2,%3};"
        : "+f"(c[0]), "+f"(c[1]), "+f"(c[2]), "+f"(c[3])
        : "r"(a[0]), "r"(a[1]), "r"(a[2]), "r"(a[3]), "r"(b[0]), "r"(b[1]));
}

// D = A*B + 0 (fresh accumulation chain)
__device__ __forceinline__ void mma_f16_zero(float* d, const uint32_t* a, const uint32_t* b) {
    asm volatile(
        "mma.sync.aligned.m16n8k16.row.col.f32.f16.f16.f32 "
        "{%0,%1,%2,%3}, {%4,%5,%6,%7}, {%8,%9}, {%10,%11,%12,%13};"
        : "=f"(d[0]), "=f"(d[1]), "=f"(d[2]), "=f"(d[3])
        : "r"(a[0]), "r"(a[1]), "r"(a[2]), "r"(a[3]), "r"(b[0]), "r"(b[1]),
          "f"(0.0f), "f"(0.0f), "f"(0.0f), "f"(0.0f));
}

// 3-product staged: acc += aS*bB + aB*bS + aB*bB
__device__ __forceinline__ void mma3_staged(float* acc,
                                            const uint32_t* aB, const uint32_t* aS,
                                            const uint32_t* bB, const uint32_t* bS) {
    float tmp[4];
    mma_f16_zero(tmp, aS, bB);
    mma_f16(tmp, aB, bS);
    mma_f16(tmp, aB, bB);
    acc[0] += tmp[0];
    acc[1] += tmp[1];
    acc[2] += tmp[2];
    acc[3] += tmp[3];
}

// ============================================================================
// Shared staged-GEMM body: C = alpha * A * B^T, fp16x2 3-product split.
// ============================================================================
__device__ __forceinline__
void gemm_abt3_body(const float* __restrict__ A, const float* __restrict__ B,
                    float* __restrict__ C,
                    int K, int lda, int ldb, int ldc,
                    int bx, int by, float alpha)
{
    __shared__ uint32_t AsB[8][SPAD];
    __shared__ uint32_t AsS[8][SPAD];
    __shared__ uint32_t BsB[8][SPAD];
    __shared__ uint32_t BsS[8][SPAD];

    const int tid  = threadIdx.x;
    const int lane = tid & 31;
    const int wid  = tid >> 5;
    const int g    = lane >> 2;
    const int tig  = lane & 3;
    const int mbase = (wid >> 2) * 64;
    const int nbase = (wid & 3) * 32;

    const int lrow = tid >> 2;
    const int lcol = (tid & 3) * 4;
    const int kp0  = lcol >> 1;

    const float* Ab = A + (long)(by * 128) * lda;
    const float* Bb = B + (long)(bx * 128) * ldb;

    float acc[4][4][4];
#pragma unroll
    for (int i = 0; i < 4; i++)
#pragma unroll
        for (int j = 0; j < 4; j++)
#pragma unroll
            for (int k = 0; k < 4; k++) acc[i][j][k] = 0.0f;

    float4 ra[2], rb[2];
#pragma unroll
    for (int r = 0; r < 2; r++) {
        ra[r] = *(const float4*)(Ab + (long)(lrow + r * 64) * lda + lcol);
        rb[r] = *(const float4*)(Bb + (long)(lrow + r * 64) * ldb + lcol);
    }

    for (int kk = 0; kk < K; kk += 16) {
#pragma unroll
        for (int r = 0; r < 2; r++) {
            const int row = lrow + r * 64;
            split_pack(ra[r].x, ra[r].y, AsB[kp0    ][row], AsS[kp0    ][row]);
            split_pack(ra[r].z, ra[r].w, AsB[kp0 + 1][row], AsS[kp0 + 1][row]);
            split_pack(rb[r].x, rb[r].y, BsB[kp0    ][row], BsS[kp0    ][row]);
            split_pack(rb[r].z, rb[r].w, BsB[kp0 + 1][row], BsS[kp0 + 1][row]);
        }
        __syncthreads();

        if (kk + 16 < K) {
#pragma unroll
            for (int r = 0; r < 2; r++) {
                ra[r] = *(const float4*)(Ab + (long)(lrow + r * 64) * lda + kk + 16 + lcol);
                rb[r] = *(const float4*)(Bb + (long)(lrow + r * 64) * ldb + kk + 16 + lcol);
            }
        }

        {
            uint32_t afB[4][4], afS[4][4], bfB[4][2], bfS[4][2];
#pragma unroll
            for (int mt = 0; mt < 4; mt++) {
                const int r0 = mbase + mt * 16 + g;
                afB[mt][0] = AsB[tig    ][r0    ];
                afB[mt][1] = AsB[tig    ][r0 + 8];
                afB[mt][2] = AsB[tig + 4][r0    ];
                afB[mt][3] = AsB[tig + 4][r0 + 8];
                afS[mt][0] = AsS[tig    ][r0    ];
                afS[mt][1] = AsS[tig    ][r0 + 8];
                afS[mt][2] = AsS[tig + 4][r0    ];
                afS[mt][3] = AsS[tig + 4][r0 + 8];
            }
#pragma unroll
            for (int nt = 0; nt < 4; nt++) {
                const int c0 = nbase + nt * 8 + g;
                bfB[nt][0] = BsB[tig    ][c0];
                bfB[nt][1] = BsB[tig + 4][c0];
                bfS[nt][0] = BsS[tig    ][c0];
                bfS[nt][1] = BsS[tig + 4][c0];
            }
#pragma unroll
            for (int mt = 0; mt < 4; mt++)
#pragma unroll
                for (int nt = 0; nt < 4; nt++)
                    mma3_staged(acc[mt][nt], afB[mt], afS[mt], bfB[nt], bfS[nt]);
        }
        __syncthreads();
    }

#pragma unroll
    for (int mt = 0; mt < 4; mt++) {
#pragma unroll
        for (int nt = 0; nt < 4; nt++) {
            const int row0 = by * 128 + mbase + mt * 16 + g;
            const int col0 = bx * 128 + nbase + nt * 8 + 2 * tig;
            C[(long)row0 * ldc + col0    ] = alpha * acc[mt][nt][0];
            C[(long)row0 * ldc + col0 + 1] = alpha * acc[mt][nt][1];
            C[(long)(row0 + 8) * ldc + col0    ] = alpha * acc[mt][nt][2];
            C[(long)(row0 + 8) * ldc + col0 + 1] = alpha * acc[mt][nt][3];
        }
    }
}

// ============================================================================
// Merged Q+K projection launch: grid (32, 16, 2).
// ============================================================================
__global__ __launch_bounds__(256)
void gemm_qk_proj(const float* __restrict__ H_,
                  const float* __restrict__ Wq, const float* __restrict__ Wk,
                  float* __restrict__ Q, float* __restrict__ K_)
{
    const int z = blockIdx.z;
    if (z == 1 && blockIdx.x >= (NKV * HD) / 128) return;
    const float* B = z ? Wk : Wq;
    float*       C = z ? K_ : Q;
    const int  ldc = z ? (NKV * HD) : HID;
    gemm_abt3_body(H_, B, C, HID, HID, HID, ldc,
                   blockIdx.x, blockIdx.y, 1.0f);
}

// ============================================================================
// Scores: staged 3-product, causal. grid (16, 16, 32).
// ============================================================================
__global__ __launch_bounds__(256)
void gemm_scores3h(const float* __restrict__ Q, const float* __restrict__ K_,
                   float* __restrict__ Sm, float alpha)
{
    const int h = blockIdx.z;
    const int bx = blockIdx.x, by = blockIdx.y;
    if (bx > by) return;
    gemm_abt3_body(Q + (long)h * HD, K_ + (long)(h >> 2) * HD,
                   Sm + (long)h * S_LEN * S_LEN,
                   HD, HID, NKV * HD, S_LEN, bx, by, alpha);
}

// ============================================================================
// Plain fp16 GEMM: C = alpha * A * B^T  (Wv, Wo projections; Output 0 only)
// ============================================================================
__global__ __launch_bounds__(256)
void gemm_abt_f16(const float* __restrict__ A, const float* __restrict__ B,
                  float* __restrict__ C,
                  int K, int lda, int ldb, int ldc, float alpha)
{
    const int bx = blockIdx.x, by = blockIdx.y;

    __shared__ uint32_t As[8][SPAD];
    __shared__ uint32_t Bs[8][SPAD];

    const int tid  = threadIdx.x;
    const int lane = tid & 31;
    const int wid  = tid >> 5;
    const int g    = lane >> 2;
    const int tig  = lane & 3;
    const int mbase = (wid >> 2) * 64;
    const int nbase = (wid & 3) * 32;

    const int lrow = tid >> 2;
    const int lcol = (tid & 3) * 4;
    const int kp0  = lcol >> 1;

    const float* Ab = A + (long)(by * 128) * lda;
    const float* Bb = B + (long)(bx * 128) * ldb;

    float acc[4][4][4];
#pragma unroll
    for (int i = 0; i < 4; i++)
#pragma unroll
        for (int j = 0; j < 4; j++)
#pragma unroll
            for (int k = 0; k < 4; k++) acc[i][j][k] = 0.0f;

    float4 ra[2], rb[2];
#pragma unroll
    for (int r = 0; r < 2; r++) {
        ra[r] = *(const float4*)(Ab + (long)(lrow + r * 64) * lda + lcol);
        rb[r] = *(const float4*)(Bb + (long)(lrow + r * 64) * ldb + lcol);
    }

    for (int kk = 0; kk < K; kk += 16) {
#pragma unroll
        for (int r = 0; r < 2; r++) {
            const int row = lrow + r * 64;
            As[kp0    ][row] = f2h2(ra[r].x, ra[r].y);
            As[kp0 + 1][row] = f2h2(ra[r].z, ra[r].w);
            Bs[kp0    ][row] = f2h2(rb[r].x, rb[r].y);
            Bs[kp0 + 1][row] = f2h2(rb[r].z, rb[r].w);
        }
        __syncthreads();

        if (kk + 16 < K) {
#pragma unroll
            for (int r = 0; r < 2; r++) {
                ra[r] = *(const float4*)(Ab + (long)(lrow + r * 64) * lda + kk + 16 + lcol);
                rb[r] = *(const float4*)(Bb + (long)(lrow + r * 64) * ldb + kk + 16 + lcol);
            }
        }

        {
            uint32_t af[4][4], bf[4][2];
#pragma unroll
            for (int mt = 0; mt < 4; mt++) {
                const int r0 = mbase + mt * 16 + g;
                af[mt][0] = As[tig    ][r0    ];
                af[mt][1] = As[tig    ][r0 + 8];
                af[mt][2] = As[tig + 4][r0    ];
                af[mt][3] = As[tig + 4][r0 + 8];
            }
#pragma unroll
            for (int nt = 0; nt < 4; nt++) {
                const int c0 = nbase + nt * 8 + g;
                bf[nt][0] = Bs[tig    ][c0];
                bf[nt][1] = Bs[tig + 4][c0];
            }
#pragma unroll
            for (int mt = 0; mt < 4; mt++)
#pragma unroll
                for (int nt = 0; nt < 4; nt++)
                    mma_f16(acc[mt][nt], af[mt], bf[nt]);
        }
        __syncthreads();
    }

#pragma unroll
    for (int mt = 0; mt < 4; mt++) {
#pragma unroll
        for (int nt = 0; nt < 4; nt++) {
            const int row0 = by * 128 + mbase + mt * 16 + g;
            const int col0 = bx * 128 + nbase + nt * 8 + 2 * tig;
            C[(long)row0 * ldc + col0    ] = alpha * acc[mt][nt][0];
            C[(long)row0 * ldc + col0 + 1] = alpha * acc[mt][nt][1];
            C[(long)(row0 + 8) * ldc + col0    ] = alpha * acc[mt][nt][2];
            C[(long)(row0 + 8) * ldc + col0 + 1] = alpha * acc[mt][nt][3];
        }
    }
}

// ============================================================================
// Plain fp16 GEMM: C = alpha * A * B  (attn * V, per-head; B row-major K x N)
// causal: K limited to (by+1)*128.
// ============================================================================
__global__ __launch_bounds__(256)
void gemm_ab_f16(const float* __restrict__ A, const float* __restrict__ B,
                 float* __restrict__ C,
                 int K, int lda, int ldb, int ldc,
                 long aHS, long bHS, long cHS, int bShift,
                 float alpha, int causal)
{
    const int h = blockIdx.z;
    A += (long)h * aHS;
    B += (long)(h >> bShift) * bHS;
    C += (long)h * cHS;
    const int bx = blockIdx.x, by = blockIdx.y;

    __shared__ uint32_t As[8][SPAD];
    __shared__ uint32_t Bs[8][SPAD];

    const int tid  = threadIdx.x;
    const int lane = tid & 31;
    const int wid  = tid >> 5;
    const int g    = lane >> 2;
    const int tig  = lane & 3;
    const int mbase = (wid >> 2) * 64;
    const int nbase = (wid & 3) * 32;

    const int lrow  = tid >> 2;
    const int lcol  = (tid & 3) * 4;
    const int kp0   = lcol >> 1;
    const int brow  = tid >> 5;
    const int bcol4 = (tid & 31) * 4;

    const float* Ab = A + (long)(by * 128) * lda;

    const int Keff = causal ? (((by + 1) * 128 < K) ? (by + 1) * 128 : K) : K;

    float acc[4][4][4];
#pragma unroll
    for (int i = 0; i < 4; i++)
#pragma unroll
        for (int j = 0; j < 4; j++)
#pragma unroll
            for (int k = 0; k < 4; k++) acc[i][j][k] = 0.0f;

    float4 ra[2], rbl, rbh;
#pragma unroll
    for (int r = 0; r < 2; r++)
        ra[r] = *(const float4*)(Ab + (long)(lrow + r * 64) * lda + lcol);
    rbl = *(const float4*)(B + (long)(2 * brow    ) * ldb + bx * 128 + bcol4);
    rbh = *(const float4*)(B + (long)(2 * brow + 1) * ldb + bx * 128 + bcol4);

    for (int kk = 0; kk < Keff; kk += 16) {
#pragma unroll
        for (int r = 0; r < 2; r++) {
            const int row = lrow + r * 64;
            As[kp0    ][row] = f2h2(ra[r].x, ra[r].y);
            As[kp0 + 1][row] = f2h2(ra[r].z, ra[r].w);
        }
        Bs[brow][bcol4 + 0] = f2h2(rbl.x, rbh.x);
        Bs[brow][bcol4 + 1] = f2h2(rbl.y, rbh.y);
        Bs[brow][bcol4 + 2] = f2h2(rbl.z, rbh.z);
        Bs[brow][bcol4 + 3] = f2h2(rbl.w, rbh.w);
        __syncthreads();

        if (kk + 16 < Keff) {
#pragma unroll
            for (int r = 0; r < 2; r++)
                ra[r] = *(const float4*)(Ab + (long)(lrow + r * 64) * lda + kk + 16 + lcol);
            rbl = *(const float4*)(B + (long)(kk + 16 + 2 * brow    ) * ldb + bx * 128 + bcol4);
            rbh = *(const float4*)(B + (long)(kk + 16 + 2 * brow + 1) * ldb + bx * 128 + bcol4);
        }

        {
            uint32_t af[4][4], bf[4][2];
#pragma unroll
            for (int mt = 0; mt < 4; mt++) {
                const int r0 = mbase + mt * 16 + g;
                af[mt][0] = As[tig    ][r0    ];
                af[mt][1] = As[tig    ][r0 + 8];
                af[mt][2] = As[tig + 4][r0    ];
                af[mt][3] = As[tig + 4][r0 + 8];
            }
#pragma unroll
            for (int nt = 0; nt < 4; nt++) {
                const int c0 = nbase + nt * 8 + g;
                bf[nt][0] = Bs[tig    ][c0];
                bf[nt][1] = Bs[tig + 4][c0];
            }
#pragma unroll
            for (int mt = 0; mt < 4; mt++)
#pragma unroll
                for (int nt = 0; nt < 4; nt++)
                    mma_f16(acc[mt][nt], af[mt], bf[nt]);
        }
        __syncthreads();
    }

#pragma unroll
    for (int mt = 0; mt < 4; mt++) {
#pragma unroll
        for (int nt = 0; nt < 4; nt++) {
            const int row0 = by * 128 + mbase + mt * 16 + g;
            const int col0 = bx * 128 + nbase + nt * 8 + 2 * tig;
            C[(long)row0 * ldc + col0    ] = alpha * acc[mt][nt][0];
            C[(long)row0 * ldc + col0 + 1] = alpha * acc[mt][nt][1];
            C[(long)(row0 + 8) * ldc + col0    ] = alpha * acc[mt][nt][2];
            C[(long)(row0 + 8) * ldc + col0 + 1] = alpha * acc[mt][nt][3];
        }
    }
}

// ============================================================================
// Merged RoPE: first totQ threads handle Q (nh=NH), rest handle K (nh=NKV).
// ============================================================================
__global__ void rope_both_kernel(float* __restrict__ Q, float* __restrict__ K_,
                                 int totQ, int totAll)
{
    int idx = blockIdx.x * blockDim.x + threadIdx.x;
    if (idx >= totAll) return;
    float* X;
    int nh;
    if (idx < totQ) { X = Q;  nh = NH;  }
    else            { X = K_; nh = NKV; idx -= totQ; }
    int d = idx & 63;
    int h = (idx >> 6) % nh;
    int s = idx / (64 * nh);
    float e    = (float)(2 * d) * (1.0f / 128.0f);
    float invf = 1.0f / powf(10000.0f, e);
    float ang  = (float)s * invf;
    float c = cosf(ang), sn = sinf(ang);
    float* p = X + (long)s * (nh * HD) + h * HD;
    float x1 = p[d], x2 = p[d + 64];
    p[d]      = x1 * c - x2 * sn;
    p[d + 64] = x2 * c + x1 * sn;
}

// ============================================================================
// Causal row softmax, online max/sum with __expf; zero-fills diagonal block.
// ============================================================================
__global__ __launch_bounds__(256)
void softmax_causal(float* __restrict__ Sm)
{
    const int q = blockIdx.x, h = blockIdx.y;
    float* row = Sm + ((long)h * S_LEN + q) * S_LEN;
    const int len = q + 1;
    const int tid = threadIdx.x;
    __shared__ float mred[256], sred[256];

    float m = -INFINITY, s = 0.0f;
    for (int i = tid; i < len; i += 256) {
        float x = row[i];
        float nm = fmaxf(m, x);
        s = s * __expf(m - nm) + __expf(x - nm);
        m = nm;
    }
    mred[tid] = m; sred[tid] = s; __syncthreads();
    for (int st = 128; st > 0; st >>= 1) {
        if (tid < st) {
            float m1 = mred[tid], s1 = sred[tid];
            float m2 = mred[tid + st], s2 = sred[tid + st];
            float nm = fmaxf(m1, m2);
            float sm = 0.0f;
            if (m1 > -INFINITY) sm += s1 * __expf(m1 - nm);
            if (m2 > -INFINITY) sm += s2 * __expf(m2 - nm);
            mred[tid] = nm; sred[tid] = sm;
        }
        __syncthreads();
    }
    const float M = mred[0];
    const float inv = 1.0f / sred[0];

    for (int i = tid; i < len; i += 256) row[i] = __expf(row[i] - M) * inv;

    const int fillEnd = ((q >> 7) + 1) << 7;
    for (int i = len + tid; i < fillEnd; i += 256) row[i] = 0.0f;
}

// ============================================================================
// Column sums: cs[h][k] = sum_q attn[h][q][k] (lower triangle only).
// ============================================================================
__global__ __launch_bounds__(256)
void colsum_kernel(const float* __restrict__ attn, float* __restrict__ cs)
{
    const int k = blockIdx.x * 256 + threadIdx.x;
    const int h = blockIdx.y;
    const float* base = attn + (size_t)h * S_LEN * S_LEN;
    float s = 0.0f;
    for (int q = k; q < S_LEN; q++) s += base[(long)q * S_LEN + k];
    cs[h * S_LEN + k] = s;
}

// ============================================================================
// H2O mask: per head top-HB of colsum[0:SEL] + last RB columns.
// ============================================================================
__global__ __launch_bounds__(256)
void h2o_mask(const float* __restrict__ cs, float* __restrict__ mask)
{
    const int h = blockIdx.x;
    const int tid = threadIdx.x;
    __shared__ float vals[SEL];
    __shared__ float bval[256];
    __shared__ int   bidx[256];

    for (int i = tid; i < SEL; i += 256) vals[i] = cs[h * S_LEN + i];
    float* mrow = mask + h * (S_LEN + 1);
    for (int i = tid; i < S_LEN + 1; i += 256)
        mrow[i] = (i >= (S_LEN + 1 - RB)) ? 1.0f : 0.0f;
    __syncthreads();

    for (int it = 0; it < HB; it++) {
        float best = -INFINITY; int bi = SEL;
        for (int i = tid; i < SEL; i += 256) {
            float v = vals[i];
            if (v > best) { best = v; bi = i; }
        }
        bval[tid] = best; bidx[tid] = bi; __syncthreads();
        for (int s = 128; s > 0; s >>= 1) {
            if (tid < s) {
                if (bval[tid + s] > bval[tid] ||
                    (bval[tid + s] == bval[tid] && bidx[tid + s] < bidx[tid])) {
                    bval[tid] = bval[tid + s];
                    bidx[tid] = bidx[tid + s];
                }
            }
            __syncthreads();
        }
        if (tid == 0) {
            mrow[bidx[0]] = 1.0f;
            vals[bidx[0]] = -INFINITY;
        }
        __syncthreads();
    }
}

// ============================================================================
// Host launcher
// ============================================================================
extern "C" void kernel_launch(void* const* d_in, const int* in_sizes, int n_in,
                              void* d_out, int out_size)
{
    const float* H  = (const float*)d_in[0];
    const float* Wq = (const float*)d_in[1];
    const float* Wk = (const float*)d_in[2];
    const float* Wv = (const float*)d_in[3];
    const float* Wo = (const float*)d_in[4];
    float* out = (float*)d_out;

    float *Q, *K, *V, *Sm, *O, *CS;
    cudaGetSymbolAddress((void**)&Q,  g_Q);
    cudaGetSymbolAddress((void**)&K,  g_K);
    cudaGetSymbolAddress((void**)&V,  g_V);
    cudaGetSymbolAddress((void**)&Sm, g_S);
    cudaGetSymbolAddress((void**)&O,  g_O);
    cudaGetSymbolAddress((void**)&CS, g_CS);

    const float inv_sqrt_hd = 0.08838834764831845f; // 1/sqrt(128)

    // Q + K projections merged (same body => same footprint)
    gemm_qk_proj<<<dim3(HID / 128, S_LEN / 128, 2), 256>>>(H, Wq, Wk, Q, K);

    // V projection: plain fp16, separate launch
    gemm_abt_f16<<<dim3((NKV * HD) / 128, S_LEN / 128, 1), 256>>>(
        H, Wv, V, HID, HID, HID, NKV * HD, 1.0f);

    // RoPE (Q and K merged)
    {
        int totQ   = S_LEN * NH * 64;
        int totAll = totQ + S_LEN * NKV * 64;
        rope_both_kernel<<<(totAll + 255) / 256, 256>>>(Q, K, totQ, totAll);
    }

    // scores = Q K^T / sqrt(HD): staged 3-product, causal
    gemm_scores3h<<<dim3(S_LEN / 128, S_LEN / 128, NH), 256>>>(
        Q, K, Sm, inv_sqrt_hd);

    // softmax (online, __expf; zero-fills diagonal blocks only)
    softmax_causal<<<dim3(S_LEN, NH), 256>>>(Sm);

    // column sums
    colsum_kernel<<<dim3(S_LEN / 256, NH), 256>>>(Sm, CS);

    // context = attn * V : plain fp16
    gemm_ab_f16<<<dim3(HD / 128, S_LEN / 128, NH), 256>>>(
        Sm, V, O, S_LEN, S_LEN, NKV * HD, HID,
        (long)S_LEN * S_LEN, HD, HD, 2, 1.0f, 1);

    // attn_output = O * Wo^T : plain fp16
    gemm_abt_f16<<<dim3(HID / 128, S_LEN / 128, 1), 256>>>(
        O, Wo, out, HID, HID, HID, HID, 1.0f);

    // H2O mask
    {
        size_t maskOff = (size_t)out_size - (size_t)NH * (S_LEN + 1);
        h2o_mask<<<NH, 256>>>(CS, out + maskOff);
    }
}

// round 17
// speedup vs baseline: 1.1684x; 1.0595x over previous
#include <cuda_runtime.h>
#include <cuda_fp16.h>
#include <math.h>
#include <stdint.h>

// ----------------------------------------------------------------------------
// LlamaAttention + H2O mask. fp16 tensor-core GEMMs (m16n8k16) with ldmatrix:
//   smem operand tiles stored m-major ([128][12] u32 rows of 16 fp16) so all
//   fragment loads are ldmatrix.m8n8 (x4 for A, x2 for B) -- 3-4x fewer smem
//   ops than scalar LDS (R15 ncu: L1 71% on scores = smem-throughput bound).
//   - mask-critical path (Wq, Wk, QK^T): fp16x2 3-product staged split.
//   - Output-0-only path (Wv, attn*V, Wo): plain fp16.
// B=1, S=2048, HID=4096, NH=32, NKV=8, HD=128, GROUPS=4, HB=RB=204
// ----------------------------------------------------------------------------

#define S_LEN   2048
#define HID     4096
#define NH      32
#define NKV     8
#define HD      128
#define HB      204
#define RB      204
#define SEL     (S_LEN - RB)   // 1844
#define AST     12             // m-major smem row stride in u32 (16B-aligned rows)
#define SPAD    136            // k-major stride (attn*V B tile only)

__device__ float g_Q [S_LEN * HID];
__device__ float g_K [S_LEN * NKV * HD];
__device__ float g_V [S_LEN * NKV * HD];
__device__ float g_S [(size_t)NH * S_LEN * S_LEN];
__device__ float g_O [S_LEN * HID];
__device__ float g_CS[NH * S_LEN];

__device__ __forceinline__ uint32_t s2u(const void* p) {
    return (uint32_t)__cvta_generic_to_shared(p);
}

__device__ __forceinline__ void ldsm_x4(uint32_t* d, uint32_t addr) {
    asm volatile("ldmatrix.sync.aligned.m8n8.x4.shared.b16 {%0,%1,%2,%3}, [%4];"
        : "=r"(d[0]), "=r"(d[1]), "=r"(d[2]), "=r"(d[3]) : "r"(addr));
}
__device__ __forceinline__ void ldsm_x2(uint32_t* d, uint32_t addr) {
    asm volatile("ldmatrix.sync.aligned.m8n8.x2.shared.b16 {%0,%1}, [%2];"
        : "=r"(d[0]), "=r"(d[1]) : "r"(addr));
}

// pack two fp32 (consecutive k) into one fp16x2 register (low = even k)
__device__ __forceinline__ uint32_t f2h2(float lo, float hi) {
    __half2 h = __floats2half2_rn(lo, hi);
    return *reinterpret_cast<uint32_t*>(&h);
}

// split-pack: big pair + small (residual) pair
__device__ __forceinline__ void split_pack(float x0, float x1,
                                           uint32_t& bp, uint32_t& sp) {
    __half b0 = __float2half_rn(x0);
    __half b1 = __float2half_rn(x1);
    float r0 = x0 - __half2float(b0);
    float r1 = x1 - __half2float(b1);
    __half2 bb = __halves2half2(b0, b1);
    __half2 ss = __halves2half2(__float2half_rn(r0), __float2half_rn(r1));
    bp = *reinterpret_cast<uint32_t*>(&bb);
    sp = *reinterpret_cast<uint32_t*>(&ss);
}

// D += A*B  (fp16 m16n8k16, fp32 accumulate)
__device__ __forceinline__ void mma_f16(float* c, const uint32_t* a, const uint32_t* b) {
    asm volatile(
        "mma.sync.aligned.m16n8k16.row.col.f32.f16.f16.f32 "
        "{%0,%1,%2,%3}, {%4,%5,%6,%7}, {%8,%9}, {%0,%1,%2,%3};"
        : "+f"(c[0]), "+f"(c[1]), "+f"(c[2]), "+f"(c[3])
        : "r"(a[0]), "r"(a[1]), "r"(a[2]), "r"(a[3]), "r"(b[0]), "r"(b[1]));
}

// D = A*B + 0 (fresh accumulation chain)
__device__ __forceinline__ void mma_f16_zero(float* d, const uint32_t* a, const uint32_t* b) {
    asm volatile(
        "mma.sync.aligned.m16n8k16.row.col.f32.f16.f16.f32 "
        "{%0,%1,%2,%3}, {%4,%5,%6,%7}, {%8,%9}, {%10,%11,%12,%13};"
        : "=f"(d[0]), "=f"(d[1]), "=f"(d[2]), "=f"(d[3])
        : "r"(a[0]), "r"(a[1]), "r"(a[2]), "r"(a[3]), "r"(b[0]), "r"(b[1]),
          "f"(0.0f), "f"(0.0f), "f"(0.0f), "f"(0.0f));
}

// 3-product staged: acc += aS*bB + aB*bS + aB*bB
__device__ __forceinline__ void mma3_staged(float* acc,
                                            const uint32_t* aB, const uint32_t* aS,
                                            const uint32_t* bB, const uint32_t* bS) {
    float tmp[4];
    mma_f16_zero(tmp, aS, bB);
    mma_f16(tmp, aB, bS);
    mma_f16(tmp, aB, bB);
    acc[0] += tmp[0];
    acc[1] += tmp[1];
    acc[2] += tmp[2];
    acc[3] += tmp[3];
}

// ============================================================================
// Shared staged-GEMM body: C = alpha * A * B^T, fp16x2 3-product split.
// A: M x K row-major (lda), B: N x K row-major (ldb). ldmatrix operands.
// ============================================================================
__device__ __forceinline__
void gemm_abt3_body(const float* __restrict__ A, const float* __restrict__ B,
                    float* __restrict__ C,
                    int K, int lda, int ldb, int ldc,
                    int bx, int by, float alpha)
{
    __shared__ uint32_t AsB[128][AST];
    __shared__ uint32_t AsS[128][AST];
    __shared__ uint32_t BsB[128][AST];
    __shared__ uint32_t BsS[128][AST];

    const int tid  = threadIdx.x;
    const int lane = tid & 31;
    const int wid  = tid >> 5;
    const int mbase = (wid >> 2) * 64;
    const int nbase = (wid & 3) * 32;

    const int lrow = tid >> 2;           // 0..63 (+64)
    const int lcol = (tid & 3) * 4;      // k offset
    const int kp0  = lcol >> 1;          // k-pair col 0,2,4,6

    const float* Ab = A + (long)(by * 128) * lda;
    const float* Bb = B + (long)(bx * 128) * ldb;

    // ldmatrix per-thread row pointers
    const int arow = mbase + (lane & 15);
    const int acol = (lane >> 4) * 4;
    const uint32_t aB0 = s2u(&AsB[arow][acol]);
    const uint32_t aS0 = s2u(&AsS[arow][acol]);
    const int brow = nbase + (lane & 7);
    const int bcol = ((lane >> 3) & 1) * 4;
    const uint32_t bB0 = s2u(&BsB[brow][bcol]);
    const uint32_t bS0 = s2u(&BsS[brow][bcol]);

    float acc[4][4][4];
#pragma unroll
    for (int i = 0; i < 4; i++)
#pragma unroll
        for (int j = 0; j < 4; j++)
#pragma unroll
            for (int k = 0; k < 4; k++) acc[i][j][k] = 0.0f;

    float4 ra[2], rb[2];
#pragma unroll
    for (int r = 0; r < 2; r++) {
        ra[r] = *(const float4*)(Ab + (long)(lrow + r * 64) * lda + lcol);
        rb[r] = *(const float4*)(Bb + (long)(lrow + r * 64) * ldb + lcol);
    }

    for (int kk = 0; kk < K; kk += 16) {
#pragma unroll
        for (int r = 0; r < 2; r++) {
            const int row = lrow + r * 64;
            uint2 vb, vs;
            split_pack(ra[r].x, ra[r].y, vb.x, vs.x);
            split_pack(ra[r].z, ra[r].w, vb.y, vs.y);
            *(uint2*)&AsB[row][kp0] = vb;
            *(uint2*)&AsS[row][kp0] = vs;
            split_pack(rb[r].x, rb[r].y, vb.x, vs.x);
            split_pack(rb[r].z, rb[r].w, vb.y, vs.y);
            *(uint2*)&BsB[row][kp0] = vb;
            *(uint2*)&BsS[row][kp0] = vs;
        }
        __syncthreads();

        if (kk + 16 < K) {
#pragma unroll
            for (int r = 0; r < 2; r++) {
                ra[r] = *(const float4*)(Ab + (long)(lrow + r * 64) * lda + kk + 16 + lcol);
                rb[r] = *(const float4*)(Bb + (long)(lrow + r * 64) * ldb + kk + 16 + lcol);
            }
        }

        {
            uint32_t afB[4][4], afS[4][4], bfB[4][2], bfS[4][2];
#pragma unroll
            for (int mt = 0; mt < 4; mt++) {
                ldsm_x4(afB[mt], aB0 + mt * 16 * AST * 4);
                ldsm_x4(afS[mt], aS0 + mt * 16 * AST * 4);
            }
#pragma unroll
            for (int nt = 0; nt < 4; nt++) {
                ldsm_x2(bfB[nt], bB0 + nt * 8 * AST * 4);
                ldsm_x2(bfS[nt], bS0 + nt * 8 * AST * 4);
            }
#pragma unroll
            for (int mt = 0; mt < 4; mt++)
#pragma unroll
                for (int nt = 0; nt < 4; nt++)
                    mma3_staged(acc[mt][nt], afB[mt], afS[mt], bfB[nt], bfS[nt]);
        }
        __syncthreads();
    }

    const int g   = lane >> 2;
    const int tig = lane & 3;
#pragma unroll
    for (int mt = 0; mt < 4; mt++) {
#pragma unroll
        for (int nt = 0; nt < 4; nt++) {
            const int row0 = by * 128 + mbase + mt * 16 + g;
            const int col0 = bx * 128 + nbase + nt * 8 + 2 * tig;
            C[(long)row0 * ldc + col0    ] = alpha * acc[mt][nt][0];
            C[(long)row0 * ldc + col0 + 1] = alpha * acc[mt][nt][1];
            C[(long)(row0 + 8) * ldc + col0    ] = alpha * acc[mt][nt][2];
            C[(long)(row0 + 8) * ldc + col0 + 1] = alpha * acc[mt][nt][3];
        }
    }
}

// ============================================================================
// Merged Q+K projection launch: grid (32, 16, 2).
// ============================================================================
__global__ __launch_bounds__(256)
void gemm_qk_proj(const float* __restrict__ H_,
                  const float* __restrict__ Wq, const float* __restrict__ Wk,
                  float* __restrict__ Q, float* __restrict__ K_)
{
    const int z = blockIdx.z;
    if (z == 1 && blockIdx.x >= (NKV * HD) / 128) return;
    const float* B = z ? Wk : Wq;
    float*       C = z ? K_ : Q;
    const int  ldc = z ? (NKV * HD) : HID;
    gemm_abt3_body(H_, B, C, HID, HID, HID, ldc,
                   blockIdx.x, blockIdx.y, 1.0f);
}

// ============================================================================
// Scores: staged 3-product, causal. grid (16, 16, 32).
// ============================================================================
__global__ __launch_bounds__(256)
void gemm_scores3h(const float* __restrict__ Q, const float* __restrict__ K_,
                   float* __restrict__ Sm, float alpha)
{
    const int h = blockIdx.z;
    const int bx = blockIdx.x, by = blockIdx.y;
    if (bx > by) return;
    gemm_abt3_body(Q + (long)h * HD, K_ + (long)(h >> 2) * HD,
                   Sm + (long)h * S_LEN * S_LEN,
                   HD, HID, NKV * HD, S_LEN, bx, by, alpha);
}

// ============================================================================
// Plain fp16 GEMM: C = alpha * A * B^T  (Wv, Wo; Output 0 only). ldmatrix.
// ============================================================================
__global__ __launch_bounds__(256)
void gemm_abt_f16(const float* __restrict__ A, const float* __restrict__ B,
                  float* __restrict__ C,
                  int K, int lda, int ldb, int ldc, float alpha)
{
    const int bx = blockIdx.x, by = blockIdx.y;

    __shared__ uint32_t As[128][AST];
    __shared__ uint32_t Bs[128][AST];

    const int tid  = threadIdx.x;
    const int lane = tid & 31;
    const int wid  = tid >> 5;
    const int mbase = (wid >> 2) * 64;
    const int nbase = (wid & 3) * 32;

    const int lrow = tid >> 2;
    const int lcol = (tid & 3) * 4;
    const int kp0  = lcol >> 1;

    const float* Ab = A + (long)(by * 128) * lda;
    const float* Bb = B + (long)(bx * 128) * ldb;

    const uint32_t a0 = s2u(&As[mbase + (lane & 15)][(lane >> 4) * 4]);
    const uint32_t b0 = s2u(&Bs[nbase + (lane & 7)][((lane >> 3) & 1) * 4]);

    float acc[4][4][4];
#pragma unroll
    for (int i = 0; i < 4; i++)
#pragma unroll
        for (int j = 0; j < 4; j++)
#pragma unroll
            for (int k = 0; k < 4; k++) acc[i][j][k] = 0.0f;

    float4 ra[2], rb[2];
#pragma unroll
    for (int r = 0; r < 2; r++) {
        ra[r] = *(const float4*)(Ab + (long)(lrow + r * 64) * lda + lcol);
        rb[r] = *(const float4*)(Bb + (long)(lrow + r * 64) * ldb + lcol);
    }

    for (int kk = 0; kk < K; kk += 16) {
#pragma unroll
        for (int r = 0; r < 2; r++) {
            const int row = lrow + r * 64;
            uint2 v;
            v.x = f2h2(ra[r].x, ra[r].y);
            v.y = f2h2(ra[r].z, ra[r].w);
            *(uint2*)&As[row][kp0] = v;
            v.x = f2h2(rb[r].x, rb[r].y);
            v.y = f2h2(rb[r].z, rb[r].w);
            *(uint2*)&Bs[row][kp0] = v;
        }
        __syncthreads();

        if (kk + 16 < K) {
#pragma unroll
            for (int r = 0; r < 2; r++) {
                ra[r] = *(const float4*)(Ab + (long)(lrow + r * 64) * lda + kk + 16 + lcol);
                rb[r] = *(const float4*)(Bb + (long)(lrow + r * 64) * ldb + kk + 16 + lcol);
            }
        }

        {
            uint32_t af[4][4], bf[4][2];
#pragma unroll
            for (int mt = 0; mt < 4; mt++)
                ldsm_x4(af[mt], a0 + mt * 16 * AST * 4);
#pragma unroll
            for (int nt = 0; nt < 4; nt++)
                ldsm_x2(bf[nt], b0 + nt * 8 * AST * 4);
#pragma unroll
            for (int mt = 0; mt < 4; mt++)
#pragma unroll
                for (int nt = 0; nt < 4; nt++)
                    mma_f16(acc[mt][nt], af[mt], bf[nt]);
        }
        __syncthreads();
    }

    const int g   = lane >> 2;
    const int tig = lane & 3;
#pragma unroll
    for (int mt = 0; mt < 4; mt++) {
#pragma unroll
        for (int nt = 0; nt < 4; nt++) {
            const int row0 = by * 128 + mbase + mt * 16 + g;
            const int col0 = bx * 128 + nbase + nt * 8 + 2 * tig;
            C[(long)row0 * ldc + col0    ] = alpha * acc[mt][nt][0];
            C[(long)row0 * ldc + col0 + 1] = alpha * acc[mt][nt][1];
            C[(long)(row0 + 8) * ldc + col0    ] = alpha * acc[mt][nt][2];
            C[(long)(row0 + 8) * ldc + col0 + 1] = alpha * acc[mt][nt][3];
        }
    }
}

// ============================================================================
// Plain fp16 GEMM: C = alpha * A * B  (attn * V, per-head; B row-major K x N)
// A side uses ldmatrix (m-major); B side keeps k-major fill + scalar LDS.
// ============================================================================
__global__ __launch_bounds__(256)
void gemm_ab_f16(const float* __restrict__ A, const float* __restrict__ B,
                 float* __restrict__ C,
                 int K, int lda, int ldb, int ldc,
                 long aHS, long bHS, long cHS, int bShift,
                 float alpha, int causal)
{
    const int h = blockIdx.z;
    A += (long)h * aHS;
    B += (long)(h >> bShift) * bHS;
    C += (long)h * cHS;
    const int bx = blockIdx.x, by = blockIdx.y;

    __shared__ uint32_t As[128][AST];
    __shared__ uint32_t Bs[8][SPAD];

    const int tid  = threadIdx.x;
    const int lane = tid & 31;
    const int wid  = tid >> 5;
    const int g    = lane >> 2;
    const int tig  = lane & 3;
    const int mbase = (wid >> 2) * 64;
    const int nbase = (wid & 3) * 32;

    const int lrow  = tid >> 2;
    const int lcol  = (tid & 3) * 4;
    const int kp0   = lcol >> 1;
    const int brow  = tid >> 5;
    const int bcol4 = (tid & 31) * 4;

    const float* Ab = A + (long)(by * 128) * lda;

    const uint32_t a0 = s2u(&As[mbase + (lane & 15)][(lane >> 4) * 4]);

    const int Keff = causal ? (((by + 1) * 128 < K) ? (by + 1) * 128 : K) : K;

    float acc[4][4][4];
#pragma unroll
    for (int i = 0; i < 4; i++)
#pragma unroll
        for (int j = 0; j < 4; j++)
#pragma unroll
            for (int k = 0; k < 4; k++) acc[i][j][k] = 0.0f;

    float4 ra[2], rbl, rbh;
#pragma unroll
    for (int r = 0; r < 2; r++)
        ra[r] = *(const float4*)(Ab + (long)(lrow + r * 64) * lda + lcol);
    rbl = *(const float4*)(B + (long)(2 * brow    ) * ldb + bx * 128 + bcol4);
    rbh = *(const float4*)(B + (long)(2 * brow + 1) * ldb + bx * 128 + bcol4);

    for (int kk = 0; kk < Keff; kk += 16) {
#pragma unroll
        for (int r = 0; r < 2; r++) {
            const int row = lrow + r * 64;
            uint2 v;
            v.x = f2h2(ra[r].x, ra[r].y);
            v.y = f2h2(ra[r].z, ra[r].w);
            *(uint2*)&As[row][kp0] = v;
        }
        Bs[brow][bcol4 + 0] = f2h2(rbl.x, rbh.x);
        Bs[brow][bcol4 + 1] = f2h2(rbl.y, rbh.y);
        Bs[brow][bcol4 + 2] = f2h2(rbl.z, rbh.z);
        Bs[brow][bcol4 + 3] = f2h2(rbl.w, rbh.w);
        __syncthreads();

        if (kk + 16 < Keff) {
#pragma unroll
            for (int r = 0; r < 2; r++)
                ra[r] = *(const float4*)(Ab + (long)(lrow + r * 64) * lda + kk + 16 + lcol);
            rbl = *(const float4*)(B + (long)(kk + 16 + 2 * brow    ) * ldb + bx * 128 + bcol4);
            rbh = *(const float4*)(B + (long)(kk + 16 + 2 * brow + 1) * ldb + bx * 128 + bcol4);
        }

        {
            uint32_t af[4][4], bf[4][2];
#pragma unroll
            for (int mt = 0; mt < 4; mt++)
                ldsm_x4(af[mt], a0 + mt * 16 * AST * 4);
#pragma unroll
            for (int nt = 0; nt < 4; nt++) {
                const int c0 = nbase + nt * 8 + g;
                bf[nt][0] = Bs[tig    ][c0];
                bf[nt][1] = Bs[tig + 4][c0];
            }
#pragma unroll
            for (int mt = 0; mt < 4; mt++)
#pragma unroll
                for (int nt = 0; nt < 4; nt++)
                    mma_f16(acc[mt][nt], af[mt], bf[nt]);
        }
        __syncthreads();
    }

#pragma unroll
    for (int mt = 0; mt < 4; mt++) {
#pragma unroll
        for (int nt = 0; nt < 4; nt++) {
            const int row0 = by * 128 + mbase + mt * 16 + g;
            const int col0 = bx * 128 + nbase + nt * 8 + 2 * tig;
            C[(long)row0 * ldc + col0    ] = alpha * acc[mt][nt][0];
            C[(long)row0 * ldc + col0 + 1] = alpha * acc[mt][nt][1];
            C[(long)(row0 + 8) * ldc + col0    ] = alpha * acc[mt][nt][2];
            C[(long)(row0 + 8) * ldc + col0 + 1] = alpha * acc[mt][nt][3];
        }
    }
}

// ============================================================================
// Merged RoPE: first totQ threads handle Q (nh=NH), rest handle K (nh=NKV).
// ============================================================================
__global__ void rope_both_kernel(float* __restrict__ Q, float* __restrict__ K_,
                                 int totQ, int totAll)
{
    int idx = blockIdx.x * blockDim.x + threadIdx.x;
    if (idx >= totAll) return;
    float* X;
    int nh;
    if (idx < totQ) { X = Q;  nh = NH;  }
    else            { X = K_; nh = NKV; idx -= totQ; }
    int d = idx & 63;
    int h = (idx >> 6) % nh;
    int s = idx / (64 * nh);
    float e    = (float)(2 * d) * (1.0f / 128.0f);
    float invf = 1.0f / powf(10000.0f, e);
    float ang  = (float)s * invf;
    float c = cosf(ang), sn = sinf(ang);
    float* p = X + (long)s * (nh * HD) + h * HD;
    float x1 = p[d], x2 = p[d + 64];
    p[d]      = x1 * c - x2 * sn;
    p[d + 64] = x2 * c + x1 * sn;
}

// ============================================================================
// Causal row softmax, online max/sum with __expf; zero-fills diagonal block.
// ============================================================================
__global__ __launch_bounds__(256)
void softmax_causal(float* __restrict__ Sm)
{
    const int q = blockIdx.x, h = blockIdx.y;
    float* row = Sm + ((long)h * S_LEN + q) * S_LEN;
    const int len = q + 1;
    const int tid = threadIdx.x;
    __shared__ float mred[256], sred[256];

    float m = -INFINITY, s = 0.0f;
    for (int i = tid; i < len; i += 256) {
        float x = row[i];
        float nm = fmaxf(m, x);
        s = s * __expf(m - nm) + __expf(x - nm);
        m = nm;
    }
    mred[tid] = m; sred[tid] = s; __syncthreads();
    for (int st = 128; st > 0; st >>= 1) {
        if (tid < st) {
            float m1 = mred[tid], s1 = sred[tid];
            float m2 = mred[tid + st], s2 = sred[tid + st];
            float nm = fmaxf(m1, m2);
            float sm = 0.0f;
            if (m1 > -INFINITY) sm += s1 * __expf(m1 - nm);
            if (m2 > -INFINITY) sm += s2 * __expf(m2 - nm);
            mred[tid] = nm; sred[tid] = sm;
        }
        __syncthreads();
    }
    const float M = mred[0];
    const float inv = 1.0f / sred[0];

    for (int i = tid; i < len; i += 256) row[i] = __expf(row[i] - M) * inv;

    const int fillEnd = ((q >> 7) + 1) << 7;
    for (int i = len + tid; i < fillEnd; i += 256) row[i] = 0.0f;
}

// ============================================================================
// Column sums: cs[h][k] = sum_q attn[h][q][k] (lower triangle only).
// ============================================================================
__global__ __launch_bounds__(256)
void colsum_kernel(const float* __restrict__ attn, float* __restrict__ cs)
{
    const int k = blockIdx.x * 256 + threadIdx.x;
    const int h = blockIdx.y;
    const float* base = attn + (size_t)h * S_LEN * S_LEN;
    float s = 0.0f;
    for (int q = k; q < S_LEN; q++) s += base[(long)q * S_LEN + k];
    cs[h * S_LEN + k] = s;
}

// ============================================================================
// H2O mask: per head top-HB of colsum[0:SEL] + last RB columns.
// ============================================================================
__global__ __launch_bounds__(256)
void h2o_mask(const float* __restrict__ cs, float* __restrict__ mask)
{
    const int h = blockIdx.x;
    const int tid = threadIdx.x;
    __shared__ float vals[SEL];
    __shared__ float bval[256];
    __shared__ int   bidx[256];

    for (int i = tid; i < SEL; i += 256) vals[i] = cs[h * S_LEN + i];
    float* mrow = mask + h * (S_LEN + 1);
    for (int i = tid; i < S_LEN + 1; i += 256)
        mrow[i] = (i >= (S_LEN + 1 - RB)) ? 1.0f : 0.0f;
    __syncthreads();

    for (int it = 0; it < HB; it++) {
        float best = -INFINITY; int bi = SEL;
        for (int i = tid; i < SEL; i += 256) {
            float v = vals[i];
            if (v > best) { best = v; bi = i; }
        }
        bval[tid] = best; bidx[tid] = bi; __syncthreads();
        for (int s = 128; s > 0; s >>= 1) {
            if (tid < s) {
                if (bval[tid + s] > bval[tid] ||
                    (bval[tid + s] == bval[tid] && bidx[tid + s] < bidx[tid])) {
                    bval[tid] = bval[tid + s];
                    bidx[tid] = bidx[tid + s];
                }
            }
            __syncthreads();
        }
        if (tid == 0) {
            mrow[bidx[0]] = 1.0f;
            vals[bidx[0]] = -INFINITY;
        }
        __syncthreads();
    }
}

// ============================================================================
// Host launcher
// ============================================================================
extern "C" void kernel_launch(void* const* d_in, const int* in_sizes, int n_in,
                              void* d_out, int out_size)
{
    const float* H  = (const float*)d_in[0];
    const float* Wq = (const float*)d_in[1];
    const float* Wk = (const float*)d_in[2];
    const float* Wv = (const float*)d_in[3];
    const float* Wo = (const float*)d_in[4];
    float* out = (float*)d_out;

    float *Q, *K, *V, *Sm, *O, *CS;
    cudaGetSymbolAddress((void**)&Q,  g_Q);
    cudaGetSymbolAddress((void**)&K,  g_K);
    cudaGetSymbolAddress((void**)&V,  g_V);
    cudaGetSymbolAddress((void**)&Sm, g_S);
    cudaGetSymbolAddress((void**)&O,  g_O);
    cudaGetSymbolAddress((void**)&CS, g_CS);

    const float inv_sqrt_hd = 0.08838834764831845f; // 1/sqrt(128)

    // Q + K projections merged (same body => same footprint)
    gemm_qk_proj<<<dim3(HID / 128, S_LEN / 128, 2), 256>>>(H, Wq, Wk, Q, K);

    // V projection: plain fp16, separate launch
    gemm_abt_f16<<<dim3((NKV * HD) / 128, S_LEN / 128, 1), 256>>>(
        H, Wv, V, HID, HID, HID, NKV * HD, 1.0f);

    // RoPE (Q and K merged)
    {
        int totQ   = S_LEN * NH * 64;
        int totAll = totQ + S_LEN * NKV * 64;
        rope_both_kernel<<<(totAll + 255) / 256, 256>>>(Q, K, totQ, totAll);
    }

    // scores = Q K^T / sqrt(HD): staged 3-product, causal
    gemm_scores3h<<<dim3(S_LEN / 128, S_LEN / 128, NH), 256>>>(
        Q, K, Sm, inv_sqrt_hd);

    // softmax (online, __expf; zero-fills diagonal blocks only)
    softmax_causal<<<dim3(S_LEN, NH), 256>>>(Sm);

    // column sums
    colsum_kernel<<<dim3(S_LEN / 256, NH), 256>>>(Sm, CS);

    // context = attn * V : plain fp16
    gemm_ab_f16<<<dim3(HD / 128, S_LEN / 128, NH), 256>>>(
        Sm, V, O, S_LEN, S_LEN, NKV * HD, HID,
        (long)S_LEN * S_LEN, HD, HD, 2, 1.0f, 1);

    // attn_output = O * Wo^T : plain fp16
    gemm_abt_f16<<<dim3(HID / 128, S_LEN / 128, 1), 256>>>(
        O, Wo, out, HID, HID, HID, HID, 1.0f);

    // H2O mask
    {
        size_t maskOff = (size_t)out_size - (size_t)NH * (S_LEN + 1);
        h2o_mask<<<NH, 256>>>(CS, out + maskOff);
    }
}